// round 12
// baseline (speedup 1.0000x reference)
#include <cuda_runtime.h>
#include <cuda_bf16.h>
#include <math.h>
#include <stdint.h>

// ---------------------------------------------------------------------------
// Problem dims (fixed)
// ---------------------------------------------------------------------------
#define BATCH 8
#define CH    512
#define HI    32
#define WI    32
#define HO    64
#define WO    64
#define HP    66
#define WP    66
#define PLANE_O (HO*WO)          // 4096
#define CPX   1024               // channels per pixel in interleaved hi|lo layout

// ---------------------------------------------------------------------------
// Static device scratch (no allocations allowed)
// Activations: interleaved NHWC padded [b][py][px][op*512+ci], op0=hi, op1=lo
// ---------------------------------------------------------------------------
__device__ __nv_bfloat16 g_a1[(size_t)BATCH*HP*WP*CPX];
__device__ __nv_bfloat16 g_a2[(size_t)BATCH*HP*WP*CPX];
// Weights repacked: [18 (hi taps 0..8, lo taps 9..17)][cout 512][ci 512] bf16
__device__ __nv_bfloat16 g_w1p[18LL*CH*CH];
__device__ __nv_bfloat16 g_w2p[18LL*CH*CH];
__device__ float g_s1[BATCH*CH];
__device__ float g_s2[BATCH*CH];
__device__ float g_sr[BATCH*CH];
__device__ float g_d1[BATCH*CH];
__device__ float g_d2[BATCH*CH];

// ---------------------------------------------------------------------------
// PTX helpers (base-target features only: cp.async, ldmatrix, mma.sync)
// ---------------------------------------------------------------------------
__device__ __forceinline__ uint32_t smem_u32(const void* p) {
    uint32_t a;
    asm("{ .reg .u64 t; cvta.to.shared.u64 t, %1; cvt.u32.u64 %0, t; }"
        : "=r"(a) : "l"(p));
    return a;
}

__device__ __forceinline__ uint32_t pack_bf16x2(__nv_bfloat16 lo, __nv_bfloat16 hi) {
    return (uint32_t)__bfloat16_as_ushort(lo) | ((uint32_t)__bfloat16_as_ushort(hi) << 16);
}

#define CP_ASYNC16(dst, src) \
    asm volatile("cp.async.cg.shared.global [%0], [%1], 16;" \
        :: "r"(dst), "l"(src) : "memory")
#define CP_COMMIT() asm volatile("cp.async.commit_group;" ::: "memory")
#define CP_WAIT(N)  asm volatile("cp.async.wait_group %0;" :: "n"(N) : "memory")

__device__ __forceinline__ void ldsm_x4(uint32_t r[4], uint32_t addr) {
    asm volatile("ldmatrix.sync.aligned.m8n8.x4.shared.b16 {%0,%1,%2,%3}, [%4];"
        : "=r"(r[0]), "=r"(r[1]), "=r"(r[2]), "=r"(r[3]) : "r"(addr));
}

__device__ __forceinline__ void mma_bf16(float d[4], const uint32_t a[4],
                                         uint32_t b0, uint32_t b1) {
    asm volatile(
        "mma.sync.aligned.m16n8k16.row.col.f32.bf16.bf16.f32 "
        "{%0,%1,%2,%3}, {%4,%5,%6,%7}, {%8,%9}, {%0,%1,%2,%3};"
        : "+f"(d[0]), "+f"(d[1]), "+f"(d[2]), "+f"(d[3])
        : "r"(a[0]), "r"(a[1]), "r"(a[2]), "r"(a[3]), "r"(b0), "r"(b1));
}

// ---------------------------------------------------------------------------
// Launch 0: styles for all three mod layers. grid 48 x 256
// ---------------------------------------------------------------------------
__global__ void style_all_kernel(const float* __restrict__ w,
                                 const float* __restrict__ m1w, const float* __restrict__ m1b,
                                 const float* __restrict__ m2w, const float* __restrict__ m2b,
                                 const float* __restrict__ mrw, const float* __restrict__ mrb)
{
    int idx = blockIdx.x * 256 + threadIdx.x;    // 0 .. 3*4096
    if (idx >= 3 * BATCH * CH) return;
    int sel = idx >> 12;
    int r = idx & 4095;
    const float* mw = (sel == 0) ? m1w : (sel == 1) ? m2w : mrw;
    const float* mb = (sel == 0) ? m1b : (sel == 1) ? m2b : mrb;
    float* outp = (sel == 0) ? g_s1 : (sel == 1) ? g_s2 : g_sr;
    int b = r >> 9, c = r & 511;
    const float* wb = w + (size_t)b * CH;
    const float* mwc = mw + (size_t)c * CH;
    float acc = mb[c];
    #pragma unroll 8
    for (int t = 0; t < CH; t++) acc += wb[t] * mwc[t];
    outp[r] = acc;
}

// ---------------------------------------------------------------------------
// Launch 1: fused weight-pack + demod. grid (13312, 2), block 256.
// ---------------------------------------------------------------------------
#define WPACK_BLOCKS 9216   // 512*512*9 / 256
__global__ void wpack_demod_kernel(const float* __restrict__ w1, const float* __restrict__ w2)
{
    const int which = blockIdx.y;
    const float* wgt = which ? w2 : w1;

    if (blockIdx.x < WPACK_BLOCKS) {
        int idx = blockIdx.x * 256 + threadIdx.x;
        __nv_bfloat16* out = which ? g_w2p : g_w1p;
        int ci = idx & 511, co = (idx >> 9) & 511, tap = idx >> 18;
        float v = wgt[((size_t)co * CH + ci) * 9 + tap];
        __nv_bfloat16 h = __float2bfloat16(v);
        out[(size_t)tap * (CH * CH) + (size_t)co * CH + ci] = h;
        out[(size_t)(9 + tap) * (CH * CH) + (size_t)co * CH + ci] =
            __float2bfloat16(v - __bfloat162float(h));
        return;
    }

    // demod part: one block per (b, co)
    __shared__ float red[256];
    const float* s = which ? g_s2 : g_s1;
    float* d       = which ? g_d2 : g_d1;
    const int bc = blockIdx.x - WPACK_BLOCKS;   // 0..4095
    const int b  = bc >> 9;
    const int co = bc & 511;
    const int t  = threadIdx.x;

    float partial = 0.f;
    #pragma unroll
    for (int h = 0; h < 2; h++) {
        int ci = t + h * 256;
        const float* p = wgt + ((size_t)co * CH + ci) * 9;
        float a = 0.f;
        #pragma unroll
        for (int tap = 0; tap < 9; tap++) a += p[tap] * p[tap];
        float sv = s[b * CH + ci];
        partial += a * sv * sv;
    }
    red[t] = partial;
    __syncthreads();
    for (int off = 128; off >= 32; off >>= 1) {
        if (t < off) red[t] += red[t + off];
        __syncthreads();
    }
    if (t < 32) {
        float v = red[t];
        #pragma unroll
        for (int off = 16; off > 0; off >>= 1)
            v += __shfl_down_sync(0xffffffffu, v, off);
        if (t == 0) d[b * CH + co] = rsqrtf(v + 1e-8f);
    }
}

// ---------------------------------------------------------------------------
// Launch 2: modulate(s1) + bilinear 2x upsample -> interleaved hi|lo NHWC,
// vectorized 32B stores; border zeroing in y==64 branch. grid (8,65,8) x 256
// ---------------------------------------------------------------------------
__global__ void upsample_pack_kernel(const float* __restrict__ x)
{
    __shared__ float rows[64][2][33];
    int b = blockIdx.z, y = blockIdx.y, c0 = blockIdx.x * 64;

    if (y == 64) {
        // border zero: 260 border pixels x 1024 bf16 = 128 uint4 per buffer
        for (int i = blockIdx.x * 256 + threadIdx.x; i < 260 * 128; i += 8 * 256) {
            int u = i & 127;
            int bp = i >> 7;
            int row, col;
            if (bp < 66)       { row = 0;  col = bp; }
            else if (bp < 132) { row = 65; col = bp - 66; }
            else { int j = bp - 132; row = 1 + (j >> 1); col = (j & 1) ? 65 : 0; }
            size_t off = (((size_t)(b * HP + row)) * WP + col) * CPX;
            uint4 z = make_uint4(0, 0, 0, 0);
            ((uint4*)(g_a1 + off))[u] = z;
            ((uint4*)(g_a2 + off))[u] = z;
        }
        return;
    }

    float syf = y * 0.5f - 0.25f;
    int y0i = (int)floorf(syf);
    float fy = syf - (float)y0i;
    int ya = max(y0i, 0), yb = min(y0i + 1, HI - 1);
    for (int i = threadIdx.x; i < 64 * 2 * 32; i += 256) {
        int ci = i >> 6, r = (i >> 5) & 1, xx = i & 31;
        rows[ci][r][xx] = x[(((size_t)(b * CH + c0 + ci)) * HI + (r ? yb : ya)) * WI + xx];
    }
    __syncthreads();
    int px = threadIdx.x >> 2;
    int g  = (threadIdx.x & 3) * 16;
    float sxf = px * 0.5f - 0.25f;
    int x0i = (int)floorf(sxf);
    float fx = sxf - (float)x0i;
    int xa = max(x0i, 0), xb = min(x0i + 1, WI - 1);
    size_t obase = (((size_t)(b * HP + y + 1)) * WP + (px + 1)) * CPX + c0 + g;

    uint32_t hbuf[8], lbuf[8];
    #pragma unroll
    for (int j2 = 0; j2 < 8; j2++) {
        float vv[2];
        #pragma unroll
        for (int e = 0; e < 2; e++) {
            int ci = g + j2 * 2 + e;
            float v0 = rows[ci][0][xa] * (1.f - fx) + rows[ci][0][xb] * fx;
            float v1 = rows[ci][1][xa] * (1.f - fx) + rows[ci][1][xb] * fx;
            vv[e] = (v0 * (1.f - fy) + v1 * fy) * g_s1[b * CH + c0 + ci];
        }
        __nv_bfloat16 h0 = __float2bfloat16(vv[0]);
        __nv_bfloat16 h1 = __float2bfloat16(vv[1]);
        __nv_bfloat16 l0 = __float2bfloat16(vv[0] - __bfloat162float(h0));
        __nv_bfloat16 l1 = __float2bfloat16(vv[1] - __bfloat162float(h1));
        hbuf[j2] = pack_bf16x2(h0, h1);
        lbuf[j2] = pack_bf16x2(l0, l1);
    }
    uint4* oh = (uint4*)(g_a1 + obase);          // hi half: +0
    uint4* ol = (uint4*)(g_a1 + obase + 512);    // lo half: +512
    oh[0] = make_uint4(hbuf[0], hbuf[1], hbuf[2], hbuf[3]);
    oh[1] = make_uint4(hbuf[4], hbuf[5], hbuf[6], hbuf[7]);
    ol[0] = make_uint4(lbuf[0], lbuf[1], lbuf[2], lbuf[3]);
    ol[1] = make_uint4(lbuf[4], lbuf[5], lbuf[6], lbuf[7]);
}

// ---------------------------------------------------------------------------
// Launches 3,4: mma.sync implicit-GEMM conv3x3, bf16 hi/lo x3 split, fp32 acc.
// Block 256 thr (8 warps, 2M x 4N). Tile M=128 px, N=128 co, BK=32.
// 3 stages x 32KB => 2 CTAs/SM. ldsm addresses: 6 loop-invariant offsets,
// all 24 addresses derived via single-XOR ({0,32,64,96} folds: ks -> ^32,
// lo-half -> ^64), cutting ldsm ALU ~3x.
// ---------------------------------------------------------------------------
#define STAGE 32768
#define NSTAGE 3
#define DSMEM (NSTAGE*STAGE)
#define NITER 144            // 9 taps x 16 ci-chunks of 32

template<int PHASE>
__global__ void __launch_bounds__(256, 2)
conv_mma_kernel(const __nv_bfloat16* __restrict__ aIn,   // interleaved hi|lo
                const __nv_bfloat16* __restrict__ wp,
                const float* __restrict__ dmod,
                const float* __restrict__ nscale,
                const float* __restrict__ noise,
                const float* __restrict__ s2,
                __nv_bfloat16* __restrict__ outA,         // interleaved (PHASE 1)
                float* __restrict__ h_out)                // fp32 NCHW (PHASE 2)
{
    extern __shared__ __align__(128) char dsm[];
    __shared__ float e_d[128], e_ns[128], e_s2[128];

    const int tid = threadIdx.x;
    const int lane = tid & 31;
    const int wid = tid >> 5;
    const int warp_m = wid & 1;       // 2 x 64 pixels
    const int warp_n = wid >> 1;      // 4 x 32 couts
    const int co0 = blockIdx.x * 128;
    const int y0  = blockIdx.y * 2;   // 2 image rows = 128 pixels
    const int b   = blockIdx.z;

    const uint32_t sb = smem_u32(dsm);

    if (tid < 128) {
        e_d[tid]  = dmod[b * CH + co0 + tid];
        e_ns[tid] = nscale[co0 + tid];
        e_s2[tid] = (PHASE == 1) ? s2[b * CH + co0 + tid] : 0.f;
    }

    float acc[4][4][4] = {};

    // ---- loop-invariant ldsm offsets (relative to stage base) ----
    // base = row*128 + ((laneHi ^ (row&7))<<4); hi/lo -> ^64, ks1 -> ^32.
    const int laneHi = lane >> 4;         // 0 or 1
    uint32_t lofA[4], lofB[2];
    #pragma unroll
    for (int mt = 0; mt < 4; mt++) {
        int row = warp_m * 64 + mt * 16 + (lane & 15);
        lofA[mt] = (uint32_t)(row * 128 + ((laneHi ^ (row & 7)) << 4));
    }
    #pragma unroll
    for (int nt = 0; nt < 2; nt++) {
        int row = warp_n * 32 + nt * 16 + (lane & 15);
        lofB[nt] = (uint32_t)(16384 + row * 128 + ((laneHi ^ (row & 7)) << 4));
    }

    // ---- precomputed per-thread cp.async addressing (loop-invariant) ----
    uint32_t offA[4], dstA[4], offB[4], dstB[4];
    #pragma unroll
    for (int rep = 0; rep < 4; rep++) {
        int i = tid + rep * 256;            // 0..1023
        int row = i >> 3, col = i & 7;
        int op = col >> 2, wcol = col & 3;
        int py = y0 + (row >> 6);
        int px = row & 63;
        offA[rep] = (uint32_t)(((b * HP + py) * WP + px) * CPX + op * 512 + (wcol << 3));
        dstA[rep] = (uint32_t)(row * 128 + ((col ^ (row & 7)) << 4));
        offB[rep] = (uint32_t)((((op * 9) * CH + co0 + row) << 9) + (wcol << 3));
        dstB[rep] = (uint32_t)(16384 + row * 128 + ((col ^ (row & 7)) << 4));
    }

    auto issue = [&](int it, int buf) {
        const int tap = it >> 4;            // 0..8
        const int ci0 = (it & 15) << 5;     // 0..480
        const int dy = (tap * 171) >> 9;    // tap/3
        const int dx = tap - dy * 3;
        const uint32_t aDelta = (uint32_t)((dy * WP + dx) * CPX + ci0);
        const uint32_t bDelta = (uint32_t)((tap << 18) + ci0);   // tap*CH*512
        const uint32_t S = sb + buf * STAGE;
        const __nv_bfloat16* ga = aIn + aDelta;
        const __nv_bfloat16* gb = wp + bDelta;
        #pragma unroll
        for (int rep = 0; rep < 4; rep++) CP_ASYNC16(S + dstA[rep], ga + offA[rep]);
        #pragma unroll
        for (int rep = 0; rep < 4; rep++) CP_ASYNC16(S + dstB[rep], gb + offB[rep]);
        CP_COMMIT();
    };

    issue(0, 0);
    issue(1, 1);

    int cur = 0;          // stage of iteration it
    int nx2 = 2;          // stage of iteration it+2
    #pragma unroll 1
    for (int it = 0; it < NITER; ++it) {
        CP_WAIT(1);              // groups 0..it complete; it+1 may be in flight
        __syncthreads();

        const uint32_t S = sb + cur * STAGE;
        uint32_t bA[4], bB[2];
        #pragma unroll
        for (int mt = 0; mt < 4; mt++) bA[mt] = S + lofA[mt];
        #pragma unroll
        for (int nt = 0; nt < 2; nt++) bB[nt] = S + lofB[nt];

        #pragma unroll
        for (int ks = 0; ks < 2; ks++) {
            const uint32_t kx = ks ? 32u : 0u;
            uint32_t ah[4][4], al[4][4], bh[2][4], bl[2][4];
            #pragma unroll
            for (int mt = 0; mt < 4; mt++) {
                ldsm_x4(ah[mt], bA[mt] ^ kx);
                ldsm_x4(al[mt], bA[mt] ^ (kx | 64u));
            }
            #pragma unroll
            for (int nt = 0; nt < 2; nt++) {
                ldsm_x4(bh[nt], bB[nt] ^ kx);
                ldsm_x4(bl[nt], bB[nt] ^ (kx | 64u));
            }
            #pragma unroll
            for (int prod = 0; prod < 3; prod++)
                #pragma unroll
                for (int mt = 0; mt < 4; mt++)
                    #pragma unroll
                    for (int nt = 0; nt < 2; nt++)
                        #pragma unroll
                        for (int hf = 0; hf < 2; hf++) {
                            float* d = acc[mt][nt * 2 + hf];
                            const uint32_t* a = (prod == 1) ? al[mt] : ah[mt];
                            uint32_t b0 = (prod == 2) ? bl[nt][hf]     : bh[nt][hf];
                            uint32_t b1 = (prod == 2) ? bl[nt][hf + 2] : bh[nt][hf + 2];
                            mma_bf16(d, a, b0, b1);
                        }

            // issue stage it+2 into the slot freed by iteration it-1
            if (ks == 0 && it + 2 < NITER) issue(it + 2, nx2);
        }

        if (++cur == NSTAGE) cur = 0;
        if (++nx2 == NSTAGE) nx2 = 0;
    }

    // -------- epilogue --------
    #pragma unroll
    for (int mt = 0; mt < 4; mt++) {
        #pragma unroll
        for (int rr = 0; rr < 2; rr++) {
            int m = warp_m * 64 + mt * 16 + rr * 8 + (lane >> 2);
            int py = y0 + (m >> 6);
            int px = m & 63;
            float nz = noise[(size_t)b * PLANE_O + py * WO + px];
            #pragma unroll
            for (int nj = 0; nj < 4; nj++) {
                int nrel = warp_n * 32 + nj * 8 + (lane & 3) * 2;
                float v0 = acc[mt][nj][rr * 2 + 0] * e_d[nrel]     + e_ns[nrel]     * nz;
                float v1 = acc[mt][nj][rr * 2 + 1] * e_d[nrel + 1] + e_ns[nrel + 1] * nz;
                v0 = (v0 >= 0.f) ? v0 : 0.2f * v0;
                v1 = (v1 >= 0.f) ? v1 : 0.2f * v1;
                if (PHASE == 1) {
                    v0 *= e_s2[nrel];
                    v1 *= e_s2[nrel + 1];
                    __nv_bfloat16 h0 = __float2bfloat16(v0);
                    __nv_bfloat16 h1 = __float2bfloat16(v1);
                    __nv_bfloat16 l0 = __float2bfloat16(v0 - __bfloat162float(h0));
                    __nv_bfloat16 l1 = __float2bfloat16(v1 - __bfloat162float(h1));
                    size_t o = ((((size_t)b * HP + py + 1) * WP) + px + 1) * CPX + co0 + nrel;
                    *(uint32_t*)(outA + o)       = pack_bf16x2(h0, h1);
                    *(uint32_t*)(outA + o + 512) = pack_bf16x2(l0, l1);
                } else {
                    size_t o = ((size_t)b * CH + co0 + nrel) * PLANE_O + py * WO + px;
                    h_out[o] = v0;
                    h_out[o + PLANE_O] = v1;
                }
            }
        }
    }
}

// ---------------------------------------------------------------------------
// Launch 5: to-RGB 1x1 conv
// ---------------------------------------------------------------------------
__global__ void rgb_kernel(const float* __restrict__ h, const float* __restrict__ rgbw,
                           float* __restrict__ rgb)
{
    __shared__ float weff[3 * CH];
    int b = blockIdx.y;
    for (int i = threadIdx.x; i < 3 * CH; i += 256) {
        int c = i / CH, ci = i % CH;
        weff[i] = rgbw[c * CH + ci] * g_sr[b * CH + ci];
    }
    __syncthreads();
    int pix = blockIdx.x * 256 + threadIdx.x;
    const float* hb = h + (size_t)b * CH * PLANE_O + pix;
    float a0 = 0.f, a1 = 0.f, a2 = 0.f;
    #pragma unroll 4
    for (int ci = 0; ci < CH; ci++) {
        float hv = hb[(size_t)ci * PLANE_O];
        a0 += weff[ci] * hv;
        a1 += weff[CH + ci] * hv;
        a2 += weff[2 * CH + ci] * hv;
    }
    float* rb = rgb + (size_t)b * 3 * PLANE_O + pix;
    rb[0] = a0; rb[PLANE_O] = a1; rb[2 * PLANE_O] = a2;
}

// ---------------------------------------------------------------------------
// host launch
// ---------------------------------------------------------------------------
extern "C" void kernel_launch(void* const* d_in, const int* in_sizes, int n_in,
                              void* d_out, int out_size)
{
    const float* x   = (const float*)d_in[0];
    const float* w   = (const float*)d_in[1];
    const float* w1  = (const float*)d_in[2];
    const float* m1w = (const float*)d_in[3];
    const float* m1b = (const float*)d_in[4];
    const float* ns1 = (const float*)d_in[5];
    const float* w2  = (const float*)d_in[6];
    const float* m2w = (const float*)d_in[7];
    const float* m2b = (const float*)d_in[8];
    const float* ns2 = (const float*)d_in[9];
    const float* wr  = (const float*)d_in[10];
    const float* mrw = (const float*)d_in[11];
    const float* mrb = (const float*)d_in[12];
    const float* n1  = (const float*)d_in[13];
    const float* n2  = (const float*)d_in[14];

    float* out     = (float*)d_out;
    float* h_out   = out;                                  // [8,512,64,64]
    float* rgb_out = out + (size_t)BATCH * CH * PLANE_O;   // [8,3,64,64]

    float *p_s2, *p_d1, *p_d2;
    __nv_bfloat16 *p_a1, *p_a2, *p_w1p, *p_w2p;
    cudaGetSymbolAddress((void**)&p_s2, g_s2);
    cudaGetSymbolAddress((void**)&p_d1, g_d1);
    cudaGetSymbolAddress((void**)&p_d2, g_d2);
    cudaGetSymbolAddress((void**)&p_a1, g_a1);
    cudaGetSymbolAddress((void**)&p_a2, g_a2);
    cudaGetSymbolAddress((void**)&p_w1p, g_w1p);
    cudaGetSymbolAddress((void**)&p_w2p, g_w2p);

    cudaFuncSetAttribute(conv_mma_kernel<1>, cudaFuncAttributeMaxDynamicSharedMemorySize, DSMEM);
    cudaFuncSetAttribute(conv_mma_kernel<2>, cudaFuncAttributeMaxDynamicSharedMemorySize, DSMEM);

    // 0. styles
    style_all_kernel<<<48, 256>>>(w, m1w, m1b, m2w, m2b, mrw, mrb);
    // 1. fused weight-pack + demod (both convs)
    wpack_demod_kernel<<<dim3(WPACK_BLOCKS + BATCH * CH, 2), 256>>>(w1, w2);
    // 2. modulate + upsample + border zero
    {
        dim3 g(8, 65, 8);
        upsample_pack_kernel<<<g, 256>>>(x);
    }
    // 3. conv1 (reads a1, writes conv2 input a2, pre-modulated by s2)
    {
        dim3 g(4, 32, 8);
        conv_mma_kernel<1><<<g, 256, DSMEM>>>(p_a1, p_w1p, p_d1, ns1, n1,
                                              p_s2, p_a2, nullptr);
    }
    // 4. conv2 (reads a2, writes h_out fp32)
    {
        dim3 g(4, 32, 8);
        conv_mma_kernel<2><<<g, 256, DSMEM>>>(p_a2, p_w2p, p_d2, ns2, n2,
                                              nullptr, nullptr, h_out);
    }
    // 5. rgb
    {
        dim3 g(PLANE_O / 256, BATCH);
        rgb_kernel<<<g, 256>>>(h_out, wr, rgb_out);
    }
    (void)in_sizes; (void)n_in; (void)out_size;
}

// round 13
// speedup vs baseline: 1.5107x; 1.5107x over previous
#include <cuda_runtime.h>
#include <cuda_fp16.h>
#include <math.h>
#include <stdint.h>

// ---------------------------------------------------------------------------
// Problem dims (fixed)
// ---------------------------------------------------------------------------
#define BATCH 8
#define CH    512
#define HI    32
#define WI    32
#define HO    64
#define WO    64
#define HP    66
#define WP    66
#define PLANE_O (HO*WO)          // 4096
#define CPX   1024               // elems per pixel: [hi 512 | lo 512] fp16

// ---------------------------------------------------------------------------
// Static device scratch (no allocations allowed)
// Activations: interleaved NHWC padded [b][py][px][op*512+ci] fp16
// Weights: [tap 0..8][cout][ci] fp16 (single rounding — 2-product scheme)
// ---------------------------------------------------------------------------
__device__ __half g_a1[(size_t)BATCH*HP*WP*CPX];
__device__ __half g_a2[(size_t)BATCH*HP*WP*CPX];
__device__ __half g_w1p[9LL*CH*CH];
__device__ __half g_w2p[9LL*CH*CH];
__device__ float g_s1[BATCH*CH];
__device__ float g_s2[BATCH*CH];
__device__ float g_sr[BATCH*CH];
__device__ float g_d1[BATCH*CH];
__device__ float g_d2[BATCH*CH];

// ---------------------------------------------------------------------------
// PTX helpers
// ---------------------------------------------------------------------------
__device__ __forceinline__ uint32_t smem_u32(const void* p) {
    uint32_t a;
    asm("{ .reg .u64 t; cvta.to.shared.u64 t, %1; cvt.u32.u64 %0, t; }"
        : "=r"(a) : "l"(p));
    return a;
}

__device__ __forceinline__ uint32_t pack_f16x2(__half lo, __half hi) {
    return (uint32_t)__half_as_ushort(lo) | ((uint32_t)__half_as_ushort(hi) << 16);
}

#define CP_ASYNC16(dst, src) \
    asm volatile("cp.async.cg.shared.global [%0], [%1], 16;" \
        :: "r"(dst), "l"(src) : "memory")
#define CP_COMMIT() asm volatile("cp.async.commit_group;" ::: "memory")
#define CP_WAIT(N)  asm volatile("cp.async.wait_group %0;" :: "n"(N) : "memory")

__device__ __forceinline__ void ldsm_x4(uint32_t r[4], uint32_t addr) {
    asm volatile("ldmatrix.sync.aligned.m8n8.x4.shared.b16 {%0,%1,%2,%3}, [%4];"
        : "=r"(r[0]), "=r"(r[1]), "=r"(r[2]), "=r"(r[3]) : "r"(addr));
}

__device__ __forceinline__ void mma_f16(float d[4], const uint32_t a[4],
                                        uint32_t b0, uint32_t b1) {
    asm volatile(
        "mma.sync.aligned.m16n8k16.row.col.f32.f16.f16.f32 "
        "{%0,%1,%2,%3}, {%4,%5,%6,%7}, {%8,%9}, {%0,%1,%2,%3};"
        : "+f"(d[0]), "+f"(d[1]), "+f"(d[2]), "+f"(d[3])
        : "r"(a[0]), "r"(a[1]), "r"(a[2]), "r"(a[3]), "r"(b0), "r"(b1));
}

// ---------------------------------------------------------------------------
// Launch 0: styles for all three mod layers. grid 48 x 256
// ---------------------------------------------------------------------------
__global__ void style_all_kernel(const float* __restrict__ w,
                                 const float* __restrict__ m1w, const float* __restrict__ m1b,
                                 const float* __restrict__ m2w, const float* __restrict__ m2b,
                                 const float* __restrict__ mrw, const float* __restrict__ mrb)
{
    int idx = blockIdx.x * 256 + threadIdx.x;
    if (idx >= 3 * BATCH * CH) return;
    int sel = idx >> 12;
    int r = idx & 4095;
    const float* mw = (sel == 0) ? m1w : (sel == 1) ? m2w : mrw;
    const float* mb = (sel == 0) ? m1b : (sel == 1) ? m2b : mrb;
    float* outp = (sel == 0) ? g_s1 : (sel == 1) ? g_s2 : g_sr;
    int b = r >> 9, c = r & 511;
    const float* wb = w + (size_t)b * CH;
    const float* mwc = mw + (size_t)c * CH;
    float acc = mb[c];
    #pragma unroll 8
    for (int t = 0; t < CH; t++) acc += wb[t] * mwc[t];
    outp[r] = acc;
}

// ---------------------------------------------------------------------------
// Launch 1: fused weight-pack (fp16) + demod. grid (13312, 2), block 256.
// ---------------------------------------------------------------------------
#define WPACK_BLOCKS 9216   // 512*512*9 / 256
__global__ void wpack_demod_kernel(const float* __restrict__ w1, const float* __restrict__ w2)
{
    const int which = blockIdx.y;
    const float* wgt = which ? w2 : w1;

    if (blockIdx.x < WPACK_BLOCKS) {
        int idx = blockIdx.x * 256 + threadIdx.x;
        __half* out = which ? g_w2p : g_w1p;
        int ci = idx & 511, co = (idx >> 9) & 511, tap = idx >> 18;
        float v = wgt[((size_t)co * CH + ci) * 9 + tap];
        out[(size_t)tap * (CH * CH) + (size_t)co * CH + ci] = __float2half(v);
        return;
    }

    // demod: one block per (b, co), from ORIGINAL fp32 weights (matches ref)
    __shared__ float red[256];
    const float* s = which ? g_s2 : g_s1;
    float* d       = which ? g_d2 : g_d1;
    const int bc = blockIdx.x - WPACK_BLOCKS;
    const int b  = bc >> 9;
    const int co = bc & 511;
    const int t  = threadIdx.x;

    float partial = 0.f;
    #pragma unroll
    for (int h = 0; h < 2; h++) {
        int ci = t + h * 256;
        const float* p = wgt + ((size_t)co * CH + ci) * 9;
        float a = 0.f;
        #pragma unroll
        for (int tap = 0; tap < 9; tap++) a += p[tap] * p[tap];
        float sv = s[b * CH + ci];
        partial += a * sv * sv;
    }
    red[t] = partial;
    __syncthreads();
    for (int off = 128; off >= 32; off >>= 1) {
        if (t < off) red[t] += red[t + off];
        __syncthreads();
    }
    if (t < 32) {
        float v = red[t];
        #pragma unroll
        for (int off = 16; off > 0; off >>= 1)
            v += __shfl_down_sync(0xffffffffu, v, off);
        if (t == 0) d[b * CH + co] = rsqrtf(v + 1e-8f);
    }
}

// ---------------------------------------------------------------------------
// Launch 2: modulate(s1) + bilinear 2x upsample -> interleaved hi|lo fp16,
// vectorized 32B stores; border zeroing in y==64 branch. grid (8,65,8) x 256
// ---------------------------------------------------------------------------
__global__ void upsample_pack_kernel(const float* __restrict__ x)
{
    __shared__ float rows[64][2][33];
    int b = blockIdx.z, y = blockIdx.y, c0 = blockIdx.x * 64;

    if (y == 64) {
        for (int i = blockIdx.x * 256 + threadIdx.x; i < 260 * 128; i += 8 * 256) {
            int u = i & 127;
            int bp = i >> 7;
            int row, col;
            if (bp < 66)       { row = 0;  col = bp; }
            else if (bp < 132) { row = 65; col = bp - 66; }
            else { int j = bp - 132; row = 1 + (j >> 1); col = (j & 1) ? 65 : 0; }
            size_t off = (((size_t)(b * HP + row)) * WP + col) * CPX;
            uint4 z = make_uint4(0, 0, 0, 0);
            ((uint4*)(g_a1 + off))[u] = z;
            ((uint4*)(g_a2 + off))[u] = z;
        }
        return;
    }

    float syf = y * 0.5f - 0.25f;
    int y0i = (int)floorf(syf);
    float fy = syf - (float)y0i;
    int ya = max(y0i, 0), yb = min(y0i + 1, HI - 1);
    for (int i = threadIdx.x; i < 64 * 2 * 32; i += 256) {
        int ci = i >> 6, r = (i >> 5) & 1, xx = i & 31;
        rows[ci][r][xx] = x[(((size_t)(b * CH + c0 + ci)) * HI + (r ? yb : ya)) * WI + xx];
    }
    __syncthreads();
    int px = threadIdx.x >> 2;
    int g  = (threadIdx.x & 3) * 16;
    float sxf = px * 0.5f - 0.25f;
    int x0i = (int)floorf(sxf);
    float fx = sxf - (float)x0i;
    int xa = max(x0i, 0), xb = min(x0i + 1, WI - 1);
    size_t obase = (((size_t)(b * HP + y + 1)) * WP + (px + 1)) * CPX + c0 + g;

    uint32_t hbuf[8], lbuf[8];
    #pragma unroll
    for (int j2 = 0; j2 < 8; j2++) {
        float vv[2];
        #pragma unroll
        for (int e = 0; e < 2; e++) {
            int ci = g + j2 * 2 + e;
            float v0 = rows[ci][0][xa] * (1.f - fx) + rows[ci][0][xb] * fx;
            float v1 = rows[ci][1][xa] * (1.f - fx) + rows[ci][1][xb] * fx;
            vv[e] = (v0 * (1.f - fy) + v1 * fy) * g_s1[b * CH + c0 + ci];
        }
        __half h0 = __float2half(vv[0]);
        __half h1 = __float2half(vv[1]);
        __half l0 = __float2half(vv[0] - __half2float(h0));
        __half l1 = __float2half(vv[1] - __half2float(h1));
        hbuf[j2] = pack_f16x2(h0, h1);
        lbuf[j2] = pack_f16x2(l0, l1);
    }
    uint4* oh = (uint4*)(g_a1 + obase);          // hi half: +0
    uint4* ol = (uint4*)(g_a1 + obase + 512);    // lo half: +512
    oh[0] = make_uint4(hbuf[0], hbuf[1], hbuf[2], hbuf[3]);
    oh[1] = make_uint4(hbuf[4], hbuf[5], hbuf[6], hbuf[7]);
    ol[0] = make_uint4(lbuf[0], lbuf[1], lbuf[2], lbuf[3]);
    ol[1] = make_uint4(lbuf[4], lbuf[5], lbuf[6], lbuf[7]);
}

// ---------------------------------------------------------------------------
// Launches 3,4: mma.sync implicit-GEMM conv3x3, fp16 A-split x2, fp32 acc.
// Block 256 thr (8 warps, 2M x 4N). Tile M=128 px, N=128 co, BK=64.
// Stage 48KB = Ah 16K | Al 16K | B 16K; 2 stages = 96KB => 2 CTAs/SM.
// Per-iter MMA: 2 products x 4mt x 2nt x 2hf x 4ks = 64/warp (was 96).
// ---------------------------------------------------------------------------
#define STAGE 49152
#define DSMEM (2*STAGE)
#define NITER 72            // 9 taps x 8 ci-chunks of 64

template<int PHASE>
__global__ void __launch_bounds__(256, 2)
conv_mma_kernel(const __half* __restrict__ aIn,   // interleaved hi|lo
                const __half* __restrict__ wp,    // fp16 weights [tap][co][ci]
                const float* __restrict__ dmod,
                const float* __restrict__ nscale,
                const float* __restrict__ noise,
                const float* __restrict__ s2,
                __half* __restrict__ outA,        // interleaved (PHASE 1)
                float* __restrict__ h_out)        // fp32 NCHW (PHASE 2)
{
    extern __shared__ __align__(128) char dsm[];
    __shared__ float e_d[128], e_ns[128], e_s2[128];

    const int tid = threadIdx.x;
    const int lane = tid & 31;
    const int wid = tid >> 5;
    const int warp_m = wid & 1;       // 2 x 64 pixels
    const int warp_n = wid >> 1;      // 4 x 32 couts
    const int co0 = blockIdx.x * 128;
    const int y0  = blockIdx.y * 2;   // 2 image rows = 128 pixels
    const int b   = blockIdx.z;

    const uint32_t sb = smem_u32(dsm);

    if (tid < 128) {
        e_d[tid]  = dmod[b * CH + co0 + tid];
        e_ns[tid] = nscale[co0 + tid];
        e_s2[tid] = (PHASE == 1) ? s2[b * CH + co0 + tid] : 0.f;
    }

    float acc[4][4][4] = {};

    // ---- affine cp.async bases (per-thread, loop-invariant) ----
    // thread covers rows r0, r0+32, r0+64, r0+96 (r0 = tid>>3), 16B col = tid&7
    const int r0  = tid >> 3;            // 0..31
    const int col = tid & 7;
    const uint32_t baseAoff =            // element offset of (y0, px=r0), hi, chunk col
        (uint32_t)(((b * HP + y0) * WP + r0) * CPX + (col << 3));
    const uint32_t baseBoff =            // tap 0 element offset
        (uint32_t)(((co0 + r0) << 9) + (col << 3));
    const uint32_t dstA0 = (uint32_t)(r0 * 128 + ((col ^ (r0 & 7)) << 4));
    const uint32_t dstB0 = dstA0 + 32768u;
    // A gmem row-step offsets (elements): rep0..3 = rows r0, r0+32 (px+32),
    // r0+64 (py+1), r0+96 (py+1, px+32)
    const uint32_t AOFF1 = 32u * CPX;            // +32 px
    const uint32_t AOFF2 = (uint32_t)WP * CPX;   // +1 py

    auto issue = [&](int it, int buf) {
        const int tap = it >> 3;            // 0..8
        const int ci0 = (it & 7) << 6;      // 0..448
        const int dy = (tap * 171) >> 9;    // tap/3
        const int dx = tap - dy * 3;
        const __half* ga = aIn + baseAoff + (uint32_t)((dy * WP + dx) * CPX + ci0);
        const __half* gb = wp + baseBoff + (uint32_t)(tap * (CH * CH) + ci0);
        const uint32_t S = sb + (uint32_t)buf * STAGE;
        const uint32_t dA = S + dstA0;
        const uint32_t dB = S + dstB0;
        #pragma unroll
        for (int rep = 0; rep < 4; rep++) {
            const uint32_t ao = (rep & 1 ? AOFF1 : 0u) + (rep >> 1 ? AOFF2 : 0u);
            CP_ASYNC16(dA + rep * 4096,          ga + ao);          // A hi
            CP_ASYNC16(dA + 16384 + rep * 4096,  ga + ao + 512);    // A lo
            CP_ASYNC16(dB + rep * 4096,          gb + rep * 16384); // B
        }
        CP_COMMIT();
    };

    issue(0, 0);

    // ---- loop-invariant ldsm row bases ----
    const int laneHi = lane >> 4;        // 0/1 -> second 16B col
    uint32_t rowA[4], rsA[4], rowB[2], rsB[2];
    #pragma unroll
    for (int mt = 0; mt < 4; mt++) {
        int row = warp_m * 64 + mt * 16 + (lane & 15);
        rowA[mt] = (uint32_t)(row * 128);
        rsA[mt]  = (uint32_t)(row & 7);
    }
    #pragma unroll
    for (int nt = 0; nt < 2; nt++) {
        int row = warp_n * 32 + nt * 16 + (lane & 15);
        rowB[nt] = (uint32_t)(32768 + row * 128);
        rsB[nt]  = (uint32_t)(row & 7);
    }

    #pragma unroll 1
    for (int it = 0; it < NITER; ++it) {
        CP_WAIT(0);              // current stage resident (1 group in flight)
        __syncthreads();

        const uint32_t S = sb + (uint32_t)(it & 1) * STAGE;

        #pragma unroll
        for (int ks = 0; ks < 4; ks++) {
            const uint32_t colA = (uint32_t)(ks * 2 + laneHi);   // 0..7
            uint32_t ah[4][4], al[4][4], bh[2][4];
            #pragma unroll
            for (int mt = 0; mt < 4; mt++) {
                uint32_t ad = S + rowA[mt] + ((colA ^ rsA[mt]) << 4);
                ldsm_x4(ah[mt], ad);
                ldsm_x4(al[mt], ad + 16384);
            }
            #pragma unroll
            for (int nt = 0; nt < 2; nt++) {
                uint32_t bd = S + rowB[nt] + ((colA ^ rsB[nt]) << 4);
                ldsm_x4(bh[nt], bd);
            }
            #pragma unroll
            for (int prod = 0; prod < 2; prod++)
                #pragma unroll
                for (int mt = 0; mt < 4; mt++)
                    #pragma unroll
                    for (int nt = 0; nt < 2; nt++)
                        #pragma unroll
                        for (int hf = 0; hf < 2; hf++) {
                            float* d = acc[mt][nt * 2 + hf];
                            const uint32_t* a = prod ? al[mt] : ah[mt];
                            mma_f16(d, a, bh[nt][hf], bh[nt][hf + 2]);
                        }

            // overlap next stage's cp.async burst with remaining MMA work
            if (ks == 0 && it + 1 < NITER) issue(it + 1, (it + 1) & 1);
        }
    }

    // -------- epilogue --------
    #pragma unroll
    for (int mt = 0; mt < 4; mt++) {
        #pragma unroll
        for (int rr = 0; rr < 2; rr++) {
            int m = warp_m * 64 + mt * 16 + rr * 8 + (lane >> 2);
            int py = y0 + (m >> 6);
            int px = m & 63;
            float nz = noise[(size_t)b * PLANE_O + py * WO + px];
            #pragma unroll
            for (int nj = 0; nj < 4; nj++) {
                int nrel = warp_n * 32 + nj * 8 + (lane & 3) * 2;
                float v0 = acc[mt][nj][rr * 2 + 0] * e_d[nrel]     + e_ns[nrel]     * nz;
                float v1 = acc[mt][nj][rr * 2 + 1] * e_d[nrel + 1] + e_ns[nrel + 1] * nz;
                v0 = (v0 >= 0.f) ? v0 : 0.2f * v0;
                v1 = (v1 >= 0.f) ? v1 : 0.2f * v1;
                if (PHASE == 1) {
                    v0 *= e_s2[nrel];
                    v1 *= e_s2[nrel + 1];
                    __half h0 = __float2half(v0);
                    __half h1 = __float2half(v1);
                    __half l0 = __float2half(v0 - __half2float(h0));
                    __half l1 = __float2half(v1 - __half2float(h1));
                    size_t o = ((((size_t)b * HP + py + 1) * WP) + px + 1) * CPX + co0 + nrel;
                    *(uint32_t*)(outA + o)       = pack_f16x2(h0, h1);
                    *(uint32_t*)(outA + o + 512) = pack_f16x2(l0, l1);
                } else {
                    size_t o = ((size_t)b * CH + co0 + nrel) * PLANE_O + py * WO + px;
                    h_out[o] = v0;
                    h_out[o + PLANE_O] = v1;
                }
            }
        }
    }
}

// ---------------------------------------------------------------------------
// Launch 5: to-RGB 1x1 conv
// ---------------------------------------------------------------------------
__global__ void rgb_kernel(const float* __restrict__ h, const float* __restrict__ rgbw,
                           float* __restrict__ rgb)
{
    __shared__ float weff[3 * CH];
    int b = blockIdx.y;
    for (int i = threadIdx.x; i < 3 * CH; i += 256) {
        int c = i / CH, ci = i % CH;
        weff[i] = rgbw[c * CH + ci] * g_sr[b * CH + ci];
    }
    __syncthreads();
    int pix = blockIdx.x * 256 + threadIdx.x;
    const float* hb = h + (size_t)b * CH * PLANE_O + pix;
    float a0 = 0.f, a1 = 0.f, a2 = 0.f;
    #pragma unroll 4
    for (int ci = 0; ci < CH; ci++) {
        float hv = hb[(size_t)ci * PLANE_O];
        a0 += weff[ci] * hv;
        a1 += weff[CH + ci] * hv;
        a2 += weff[2 * CH + ci] * hv;
    }
    float* rb = rgb + (size_t)b * 3 * PLANE_O + pix;
    rb[0] = a0; rb[PLANE_O] = a1; rb[2 * PLANE_O] = a2;
}

// ---------------------------------------------------------------------------
// host launch
// ---------------------------------------------------------------------------
extern "C" void kernel_launch(void* const* d_in, const int* in_sizes, int n_in,
                              void* d_out, int out_size)
{
    const float* x   = (const float*)d_in[0];
    const float* w   = (const float*)d_in[1];
    const float* w1  = (const float*)d_in[2];
    const float* m1w = (const float*)d_in[3];
    const float* m1b = (const float*)d_in[4];
    const float* ns1 = (const float*)d_in[5];
    const float* w2  = (const float*)d_in[6];
    const float* m2w = (const float*)d_in[7];
    const float* m2b = (const float*)d_in[8];
    const float* ns2 = (const float*)d_in[9];
    const float* wr  = (const float*)d_in[10];
    const float* mrw = (const float*)d_in[11];
    const float* mrb = (const float*)d_in[12];
    const float* n1  = (const float*)d_in[13];
    const float* n2  = (const float*)d_in[14];

    float* out     = (float*)d_out;
    float* h_out   = out;                                  // [8,512,64,64]
    float* rgb_out = out + (size_t)BATCH * CH * PLANE_O;   // [8,3,64,64]

    float *p_s2, *p_d1, *p_d2;
    __half *p_a1, *p_a2, *p_w1p, *p_w2p;
    cudaGetSymbolAddress((void**)&p_s2, g_s2);
    cudaGetSymbolAddress((void**)&p_d1, g_d1);
    cudaGetSymbolAddress((void**)&p_d2, g_d2);
    cudaGetSymbolAddress((void**)&p_a1, g_a1);
    cudaGetSymbolAddress((void**)&p_a2, g_a2);
    cudaGetSymbolAddress((void**)&p_w1p, g_w1p);
    cudaGetSymbolAddress((void**)&p_w2p, g_w2p);

    cudaFuncSetAttribute(conv_mma_kernel<1>, cudaFuncAttributeMaxDynamicSharedMemorySize, DSMEM);
    cudaFuncSetAttribute(conv_mma_kernel<2>, cudaFuncAttributeMaxDynamicSharedMemorySize, DSMEM);

    // 0. styles
    style_all_kernel<<<48, 256>>>(w, m1w, m1b, m2w, m2b, mrw, mrb);
    // 1. fused weight-pack + demod (both convs)
    wpack_demod_kernel<<<dim3(WPACK_BLOCKS + BATCH * CH, 2), 256>>>(w1, w2);
    // 2. modulate + upsample + border zero
    {
        dim3 g(8, 65, 8);
        upsample_pack_kernel<<<g, 256>>>(x);
    }
    // 3. conv1 (reads a1, writes conv2 input a2, pre-modulated by s2)
    {
        dim3 g(4, 32, 8);
        conv_mma_kernel<1><<<g, 256, DSMEM>>>(p_a1, p_w1p, p_d1, ns1, n1,
                                              p_s2, p_a2, nullptr);
    }
    // 4. conv2 (reads a2, writes h_out fp32)
    {
        dim3 g(4, 32, 8);
        conv_mma_kernel<2><<<g, 256, DSMEM>>>(p_a2, p_w2p, p_d2, ns2, n2,
                                              nullptr, nullptr, h_out);
    }
    // 5. rgb
    {
        dim3 g(PLANE_O / 256, BATCH);
        rgb_kernel<<<g, 256>>>(h_out, wr, rgb_out);
    }
    (void)in_sizes; (void)n_in; (void)out_size;
}

// round 14
// speedup vs baseline: 2.5990x; 1.7204x over previous
#include <cuda_runtime.h>
#include <cuda_fp16.h>
#include <math.h>
#include <stdint.h>

// ---------------------------------------------------------------------------
// Problem dims (fixed)
// ---------------------------------------------------------------------------
#define BATCH 8
#define CH    512
#define HI    32
#define WI    32
#define HO    64
#define WO    64
#define HP    66
#define WP    66
#define PLANE_O (HO*WO)          // 4096
#define CPX   512                // fp16 channels per pixel (plain, no split)

// ---------------------------------------------------------------------------
// Static device scratch (no allocations allowed)
// Activations: NHWC padded [b][py][px][ci] fp16
// Weights: [tap 0..8][cout][ci] fp16
// ---------------------------------------------------------------------------
__device__ __half g_a1[(size_t)BATCH*HP*WP*CPX];
__device__ __half g_a2[(size_t)BATCH*HP*WP*CPX];
__device__ __half g_w1p[9LL*CH*CH];
__device__ __half g_w2p[9LL*CH*CH];
__device__ float g_s1[BATCH*CH];
__device__ float g_s2[BATCH*CH];
__device__ float g_sr[BATCH*CH];
__device__ float g_d1[BATCH*CH];
__device__ float g_d2[BATCH*CH];

// ---------------------------------------------------------------------------
// PTX helpers
// ---------------------------------------------------------------------------
__device__ __forceinline__ uint32_t smem_u32(const void* p) {
    uint32_t a;
    asm("{ .reg .u64 t; cvta.to.shared.u64 t, %1; cvt.u32.u64 %0, t; }"
        : "=r"(a) : "l"(p));
    return a;
}

__device__ __forceinline__ uint32_t pack_f16x2(__half lo, __half hi) {
    return (uint32_t)__half_as_ushort(lo) | ((uint32_t)__half_as_ushort(hi) << 16);
}

#define CP_ASYNC16(dst, src) \
    asm volatile("cp.async.cg.shared.global [%0], [%1], 16;" \
        :: "r"(dst), "l"(src) : "memory")
#define CP_COMMIT() asm volatile("cp.async.commit_group;" ::: "memory")
#define CP_WAIT(N)  asm volatile("cp.async.wait_group %0;" :: "n"(N) : "memory")

__device__ __forceinline__ void ldsm_x4(uint32_t r[4], uint32_t addr) {
    asm volatile("ldmatrix.sync.aligned.m8n8.x4.shared.b16 {%0,%1,%2,%3}, [%4];"
        : "=r"(r[0]), "=r"(r[1]), "=r"(r[2]), "=r"(r[3]) : "r"(addr));
}

__device__ __forceinline__ void mma_f16(float d[4], const uint32_t a[4],
                                        uint32_t b0, uint32_t b1) {
    asm volatile(
        "mma.sync.aligned.m16n8k16.row.col.f32.f16.f16.f32 "
        "{%0,%1,%2,%3}, {%4,%5,%6,%7}, {%8,%9}, {%0,%1,%2,%3};"
        : "+f"(d[0]), "+f"(d[1]), "+f"(d[2]), "+f"(d[3])
        : "r"(a[0]), "r"(a[1]), "r"(a[2]), "r"(a[3]), "r"(b0), "r"(b1));
}

// ---------------------------------------------------------------------------
// Launch 0: styles for all three mod layers. grid 48 x 256
// ---------------------------------------------------------------------------
__global__ void style_all_kernel(const float* __restrict__ w,
                                 const float* __restrict__ m1w, const float* __restrict__ m1b,
                                 const float* __restrict__ m2w, const float* __restrict__ m2b,
                                 const float* __restrict__ mrw, const float* __restrict__ mrb)
{
    int idx = blockIdx.x * 256 + threadIdx.x;
    if (idx >= 3 * BATCH * CH) return;
    int sel = idx >> 12;
    int r = idx & 4095;
    const float* mw = (sel == 0) ? m1w : (sel == 1) ? m2w : mrw;
    const float* mb = (sel == 0) ? m1b : (sel == 1) ? m2b : mrb;
    float* outp = (sel == 0) ? g_s1 : (sel == 1) ? g_s2 : g_sr;
    int b = r >> 9, c = r & 511;
    const float* wb = w + (size_t)b * CH;
    const float* mwc = mw + (size_t)c * CH;
    float acc = mb[c];
    #pragma unroll 8
    for (int t = 0; t < CH; t++) acc += wb[t] * mwc[t];
    outp[r] = acc;
}

// ---------------------------------------------------------------------------
// Launch 1: fused weight-pack (fp16) + demod. grid (13312, 2), block 256.
// ---------------------------------------------------------------------------
#define WPACK_BLOCKS 9216   // 512*512*9 / 256
__global__ void wpack_demod_kernel(const float* __restrict__ w1, const float* __restrict__ w2)
{
    const int which = blockIdx.y;
    const float* wgt = which ? w2 : w1;

    if (blockIdx.x < WPACK_BLOCKS) {
        int idx = blockIdx.x * 256 + threadIdx.x;
        __half* out = which ? g_w2p : g_w1p;
        int ci = idx & 511, co = (idx >> 9) & 511, tap = idx >> 18;
        float v = wgt[((size_t)co * CH + ci) * 9 + tap];
        out[(size_t)tap * (CH * CH) + (size_t)co * CH + ci] = __float2half(v);
        return;
    }

    // demod: one block per (b, co), from ORIGINAL fp32 weights (matches ref)
    __shared__ float red[256];
    const float* s = which ? g_s2 : g_s1;
    float* d       = which ? g_d2 : g_d1;
    const int bc = blockIdx.x - WPACK_BLOCKS;
    const int b  = bc >> 9;
    const int co = bc & 511;
    const int t  = threadIdx.x;

    float partial = 0.f;
    #pragma unroll
    for (int h = 0; h < 2; h++) {
        int ci = t + h * 256;
        const float* p = wgt + ((size_t)co * CH + ci) * 9;
        float a = 0.f;
        #pragma unroll
        for (int tap = 0; tap < 9; tap++) a += p[tap] * p[tap];
        float sv = s[b * CH + ci];
        partial += a * sv * sv;
    }
    red[t] = partial;
    __syncthreads();
    for (int off = 128; off >= 32; off >>= 1) {
        if (t < off) red[t] += red[t + off];
        __syncthreads();
    }
    if (t < 32) {
        float v = red[t];
        #pragma unroll
        for (int off = 16; off > 0; off >>= 1)
            v += __shfl_down_sync(0xffffffffu, v, off);
        if (t == 0) d[b * CH + co] = rsqrtf(v + 1e-8f);
    }
}

// ---------------------------------------------------------------------------
// Launch 2: modulate(s1) + bilinear 2x upsample -> fp16 NHWC padded,
// vectorized 32B stores; border zeroing in y==64 branch. grid (8,65,8) x 256
// ---------------------------------------------------------------------------
__global__ void upsample_pack_kernel(const float* __restrict__ x)
{
    __shared__ float rows[64][2][33];
    int b = blockIdx.z, y = blockIdx.y, c0 = blockIdx.x * 64;

    if (y == 64) {
        // border zero: 260 border pixels x 512 fp16 = 64 uint4 per buffer
        for (int i = blockIdx.x * 256 + threadIdx.x; i < 260 * 64; i += 8 * 256) {
            int u = i & 63;
            int bp = i >> 6;
            int row, col;
            if (bp < 66)       { row = 0;  col = bp; }
            else if (bp < 132) { row = 65; col = bp - 66; }
            else { int j = bp - 132; row = 1 + (j >> 1); col = (j & 1) ? 65 : 0; }
            size_t off = (((size_t)(b * HP + row)) * WP + col) * CPX;
            uint4 z = make_uint4(0, 0, 0, 0);
            ((uint4*)(g_a1 + off))[u] = z;
            ((uint4*)(g_a2 + off))[u] = z;
        }
        return;
    }

    float syf = y * 0.5f - 0.25f;
    int y0i = (int)floorf(syf);
    float fy = syf - (float)y0i;
    int ya = max(y0i, 0), yb = min(y0i + 1, HI - 1);
    for (int i = threadIdx.x; i < 64 * 2 * 32; i += 256) {
        int ci = i >> 6, r = (i >> 5) & 1, xx = i & 31;
        rows[ci][r][xx] = x[(((size_t)(b * CH + c0 + ci)) * HI + (r ? yb : ya)) * WI + xx];
    }
    __syncthreads();
    int px = threadIdx.x >> 2;
    int g  = (threadIdx.x & 3) * 16;
    float sxf = px * 0.5f - 0.25f;
    int x0i = (int)floorf(sxf);
    float fx = sxf - (float)x0i;
    int xa = max(x0i, 0), xb = min(x0i + 1, WI - 1);
    size_t obase = (((size_t)(b * HP + y + 1)) * WP + (px + 1)) * CPX + c0 + g;

    uint32_t hbuf[8];
    #pragma unroll
    for (int j2 = 0; j2 < 8; j2++) {
        float vv[2];
        #pragma unroll
        for (int e = 0; e < 2; e++) {
            int ci = g + j2 * 2 + e;
            float v0 = rows[ci][0][xa] * (1.f - fx) + rows[ci][0][xb] * fx;
            float v1 = rows[ci][1][xa] * (1.f - fx) + rows[ci][1][xb] * fx;
            vv[e] = (v0 * (1.f - fy) + v1 * fy) * g_s1[b * CH + c0 + ci];
        }
        hbuf[j2] = pack_f16x2(__float2half(vv[0]), __float2half(vv[1]));
    }
    uint4* oh = (uint4*)(g_a1 + obase);
    oh[0] = make_uint4(hbuf[0], hbuf[1], hbuf[2], hbuf[3]);
    oh[1] = make_uint4(hbuf[4], hbuf[5], hbuf[6], hbuf[7]);
}

// ---------------------------------------------------------------------------
// Launches 3,4: mma.sync implicit-GEMM conv3x3, plain fp16, fp32 acc.
// Block 256 thr (8 warps, 2M x 4N). Tile M=128 px, N=128 co, BK=64.
// Stage 32KB = A 16K | B 16K; 3 stages = 96KB => 2 CTAs/SM; distance-2 issue.
// ---------------------------------------------------------------------------
#define STAGE 32768
#define NSTAGE 3
#define DSMEM (NSTAGE*STAGE)
#define NITER 72            // 9 taps x 8 ci-chunks of 64

template<int PHASE>
__global__ void __launch_bounds__(256, 2)
conv_mma_kernel(const __half* __restrict__ aIn,   // fp16 NHWC padded
                const __half* __restrict__ wp,    // fp16 weights [tap][co][ci]
                const float* __restrict__ dmod,
                const float* __restrict__ nscale,
                const float* __restrict__ noise,
                const float* __restrict__ s2,
                __half* __restrict__ outA,        // fp16 NHWC padded (PHASE 1)
                float* __restrict__ h_out)        // fp32 NCHW (PHASE 2)
{
    extern __shared__ __align__(128) char dsm[];
    __shared__ float e_d[128], e_ns[128], e_s2[128];

    const int tid = threadIdx.x;
    const int lane = tid & 31;
    const int wid = tid >> 5;
    const int warp_m = wid & 1;       // 2 x 64 pixels
    const int warp_n = wid >> 1;      // 4 x 32 couts
    const int co0 = blockIdx.x * 128;
    const int y0  = blockIdx.y * 2;   // 2 image rows = 128 pixels
    const int b   = blockIdx.z;

    const uint32_t sb = smem_u32(dsm);

    if (tid < 128) {
        e_d[tid]  = dmod[b * CH + co0 + tid];
        e_ns[tid] = nscale[co0 + tid];
        e_s2[tid] = (PHASE == 1) ? s2[b * CH + co0 + tid] : 0.f;
    }

    float acc[4][4][4] = {};

    // ---- affine cp.async bases (per-thread, loop-invariant) ----
    const int r0  = tid >> 3;            // 0..31
    const int col = tid & 7;
    const uint32_t baseAoff =
        (uint32_t)(((b * HP + y0) * WP + r0) * CPX + (col << 3));
    const uint32_t baseBoff =
        (uint32_t)(((co0 + r0) << 9) + (col << 3));
    const uint32_t dstA0 = (uint32_t)(r0 * 128 + ((col ^ (r0 & 7)) << 4));
    const uint32_t dstB0 = dstA0 + 16384u;
    const uint32_t AOFF1 = 32u * CPX;            // +32 px
    const uint32_t AOFF2 = (uint32_t)WP * CPX;   // +1 py

    auto issue = [&](int it, int buf) {
        const int tap = it >> 3;            // 0..8
        const int ci0 = (it & 7) << 6;      // 0..448
        const int dy = (tap * 171) >> 9;    // tap/3
        const int dx = tap - dy * 3;
        const __half* ga = aIn + baseAoff + (uint32_t)((dy * WP + dx) * CPX + ci0);
        const __half* gb = wp + baseBoff + (uint32_t)(tap * (CH * CH) + ci0);
        const uint32_t S = sb + (uint32_t)buf * STAGE;
        const uint32_t dA = S + dstA0;
        const uint32_t dB = S + dstB0;
        #pragma unroll
        for (int rep = 0; rep < 4; rep++) {
            const uint32_t ao = (rep & 1 ? AOFF1 : 0u) + (rep >> 1 ? AOFF2 : 0u);
            CP_ASYNC16(dA + rep * 4096, ga + ao);           // A
            CP_ASYNC16(dB + rep * 4096, gb + rep * 16384);  // B (+32 co rows)
        }
        CP_COMMIT();
    };

    issue(0, 0);
    issue(1, 1);

    // ---- loop-invariant ldsm row bases ----
    const int laneHi = lane >> 4;        // 0/1
    uint32_t rowA[4], rsA[4], rowB[2], rsB[2];
    #pragma unroll
    for (int mt = 0; mt < 4; mt++) {
        int row = warp_m * 64 + mt * 16 + (lane & 15);
        rowA[mt] = (uint32_t)(row * 128);
        rsA[mt]  = (uint32_t)(row & 7);
    }
    #pragma unroll
    for (int nt = 0; nt < 2; nt++) {
        int row = warp_n * 32 + nt * 16 + (lane & 15);
        rowB[nt] = (uint32_t)(16384 + row * 128);
        rsB[nt]  = (uint32_t)(row & 7);
    }

    int cur = 0, nx2 = 2;
    #pragma unroll 1
    for (int it = 0; it < NITER; ++it) {
        CP_WAIT(1);              // current stage resident; next may be in flight
        __syncthreads();

        const uint32_t S = sb + (uint32_t)cur * STAGE;

        #pragma unroll
        for (int ks = 0; ks < 4; ks++) {
            const uint32_t colA = (uint32_t)(ks * 2 + laneHi);   // 0..7
            uint32_t ah[4][4], bh[2][4];
            #pragma unroll
            for (int mt = 0; mt < 4; mt++)
                ldsm_x4(ah[mt], S + rowA[mt] + ((colA ^ rsA[mt]) << 4));
            #pragma unroll
            for (int nt = 0; nt < 2; nt++)
                ldsm_x4(bh[nt], S + rowB[nt] + ((colA ^ rsB[nt]) << 4));
            #pragma unroll
            for (int mt = 0; mt < 4; mt++)
                #pragma unroll
                for (int nt = 0; nt < 2; nt++)
                    #pragma unroll
                    for (int hf = 0; hf < 2; hf++)
                        mma_f16(acc[mt][nt * 2 + hf], ah[mt],
                                bh[nt][hf], bh[nt][hf + 2]);

            if (ks == 0 && it + 2 < NITER) issue(it + 2, nx2);
        }

        if (++cur == NSTAGE) cur = 0;
        if (++nx2 == NSTAGE) nx2 = 0;
    }

    // -------- epilogue --------
    #pragma unroll
    for (int mt = 0; mt < 4; mt++) {
        #pragma unroll
        for (int rr = 0; rr < 2; rr++) {
            int m = warp_m * 64 + mt * 16 + rr * 8 + (lane >> 2);
            int py = y0 + (m >> 6);
            int px = m & 63;
            float nz = noise[(size_t)b * PLANE_O + py * WO + px];
            #pragma unroll
            for (int nj = 0; nj < 4; nj++) {
                int nrel = warp_n * 32 + nj * 8 + (lane & 3) * 2;
                float v0 = acc[mt][nj][rr * 2 + 0] * e_d[nrel]     + e_ns[nrel]     * nz;
                float v1 = acc[mt][nj][rr * 2 + 1] * e_d[nrel + 1] + e_ns[nrel + 1] * nz;
                v0 = (v0 >= 0.f) ? v0 : 0.2f * v0;
                v1 = (v1 >= 0.f) ? v1 : 0.2f * v1;
                if (PHASE == 1) {
                    v0 *= e_s2[nrel];
                    v1 *= e_s2[nrel + 1];
                    size_t o = ((((size_t)b * HP + py + 1) * WP) + px + 1) * CPX + co0 + nrel;
                    *(uint32_t*)(outA + o) = pack_f16x2(__float2half(v0), __float2half(v1));
                } else {
                    size_t o = ((size_t)b * CH + co0 + nrel) * PLANE_O + py * WO + px;
                    h_out[o] = v0;
                    h_out[o + PLANE_O] = v1;
                }
            }
        }
    }
}

// ---------------------------------------------------------------------------
// Launch 5: to-RGB 1x1 conv
// ---------------------------------------------------------------------------
__global__ void rgb_kernel(const float* __restrict__ h, const float* __restrict__ rgbw,
                           float* __restrict__ rgb)
{
    __shared__ float weff[3 * CH];
    int b = blockIdx.y;
    for (int i = threadIdx.x; i < 3 * CH; i += 256) {
        int c = i / CH, ci = i % CH;
        weff[i] = rgbw[c * CH + ci] * g_sr[b * CH + ci];
    }
    __syncthreads();
    int pix = blockIdx.x * 256 + threadIdx.x;
    const float* hb = h + (size_t)b * CH * PLANE_O + pix;
    float a0 = 0.f, a1 = 0.f, a2 = 0.f;
    #pragma unroll 4
    for (int ci = 0; ci < CH; ci++) {
        float hv = hb[(size_t)ci * PLANE_O];
        a0 += weff[ci] * hv;
        a1 += weff[CH + ci] * hv;
        a2 += weff[2 * CH + ci] * hv;
    }
    float* rb = rgb + (size_t)b * 3 * PLANE_O + pix;
    rb[0] = a0; rb[PLANE_O] = a1; rb[2 * PLANE_O] = a2;
}

// ---------------------------------------------------------------------------
// host launch
// ---------------------------------------------------------------------------
extern "C" void kernel_launch(void* const* d_in, const int* in_sizes, int n_in,
                              void* d_out, int out_size)
{
    const float* x   = (const float*)d_in[0];
    const float* w   = (const float*)d_in[1];
    const float* w1  = (const float*)d_in[2];
    const float* m1w = (const float*)d_in[3];
    const float* m1b = (const float*)d_in[4];
    const float* ns1 = (const float*)d_in[5];
    const float* w2  = (const float*)d_in[6];
    const float* m2w = (const float*)d_in[7];
    const float* m2b = (const float*)d_in[8];
    const float* ns2 = (const float*)d_in[9];
    const float* wr  = (const float*)d_in[10];
    const float* mrw = (const float*)d_in[11];
    const float* mrb = (const float*)d_in[12];
    const float* n1  = (const float*)d_in[13];
    const float* n2  = (const float*)d_in[14];

    float* out     = (float*)d_out;
    float* h_out   = out;                                  // [8,512,64,64]
    float* rgb_out = out + (size_t)BATCH * CH * PLANE_O;   // [8,3,64,64]

    float *p_s2, *p_d1, *p_d2;
    __half *p_a1, *p_a2, *p_w1p, *p_w2p;
    cudaGetSymbolAddress((void**)&p_s2, g_s2);
    cudaGetSymbolAddress((void**)&p_d1, g_d1);
    cudaGetSymbolAddress((void**)&p_d2, g_d2);
    cudaGetSymbolAddress((void**)&p_a1, g_a1);
    cudaGetSymbolAddress((void**)&p_a2, g_a2);
    cudaGetSymbolAddress((void**)&p_w1p, g_w1p);
    cudaGetSymbolAddress((void**)&p_w2p, g_w2p);

    cudaFuncSetAttribute(conv_mma_kernel<1>, cudaFuncAttributeMaxDynamicSharedMemorySize, DSMEM);
    cudaFuncSetAttribute(conv_mma_kernel<2>, cudaFuncAttributeMaxDynamicSharedMemorySize, DSMEM);

    // 0. styles
    style_all_kernel<<<48, 256>>>(w, m1w, m1b, m2w, m2b, mrw, mrb);
    // 1. fused weight-pack + demod (both convs)
    wpack_demod_kernel<<<dim3(WPACK_BLOCKS + BATCH * CH, 2), 256>>>(w1, w2);
    // 2. modulate + upsample + border zero
    {
        dim3 g(8, 65, 8);
        upsample_pack_kernel<<<g, 256>>>(x);
    }
    // 3. conv1 (reads a1, writes conv2 input a2, pre-modulated by s2)
    {
        dim3 g(4, 32, 8);
        conv_mma_kernel<1><<<g, 256, DSMEM>>>(p_a1, p_w1p, p_d1, ns1, n1,
                                              p_s2, p_a2, nullptr);
    }
    // 4. conv2 (reads a2, writes h_out fp32)
    {
        dim3 g(4, 32, 8);
        conv_mma_kernel<2><<<g, 256, DSMEM>>>(p_a2, p_w2p, p_d2, ns2, n2,
                                              nullptr, nullptr, h_out);
    }
    // 5. rgb
    {
        dim3 g(PLANE_O / 256, BATCH);
        rgb_kernel<<<g, 256>>>(h_out, wr, rgb_out);
    }
    (void)in_sizes; (void)n_in; (void)out_size;
}

// round 15
// speedup vs baseline: 2.7113x; 1.0432x over previous
#include <cuda_runtime.h>
#include <cuda_fp16.h>
#include <math.h>
#include <stdint.h>

// ---------------------------------------------------------------------------
// Problem dims (fixed)
// ---------------------------------------------------------------------------
#define BATCH 8
#define CH    512
#define HI    32
#define WI    32
#define HO    64
#define WO    64
#define HP    66
#define WP    66
#define PLANE_O (HO*WO)          // 4096
#define CPX   512                // fp16 channels per pixel

// ---------------------------------------------------------------------------
// Static device scratch (no allocations allowed)
// ---------------------------------------------------------------------------
__device__ __half g_a1[(size_t)BATCH*HP*WP*CPX];
__device__ __half g_a2[(size_t)BATCH*HP*WP*CPX];
__device__ __half g_w1p[9LL*CH*CH];
__device__ __half g_w2p[9LL*CH*CH];
__device__ float g_wsq[2][CH*CH];       // sum_tap w^2 per (co,ci)
__device__ float g_s1[BATCH*CH];
__device__ float g_s2[BATCH*CH];
__device__ float g_sr[BATCH*CH];
__device__ float g_d1[BATCH*CH];
__device__ float g_d2[BATCH*CH];

// ---------------------------------------------------------------------------
// PTX helpers
// ---------------------------------------------------------------------------
__device__ __forceinline__ uint32_t smem_u32(const void* p) {
    uint32_t a;
    asm("{ .reg .u64 t; cvta.to.shared.u64 t, %1; cvt.u32.u64 %0, t; }"
        : "=r"(a) : "l"(p));
    return a;
}

__device__ __forceinline__ uint32_t pack_f16x2(__half lo, __half hi) {
    return (uint32_t)__half_as_ushort(lo) | ((uint32_t)__half_as_ushort(hi) << 16);
}

#define CP_ASYNC16(dst, src) \
    asm volatile("cp.async.cg.shared.global [%0], [%1], 16;" \
        :: "r"(dst), "l"(src) : "memory")
#define CP_COMMIT() asm volatile("cp.async.commit_group;" ::: "memory")
#define CP_WAIT(N)  asm volatile("cp.async.wait_group %0;" :: "n"(N) : "memory")

__device__ __forceinline__ void ldsm_x4(uint32_t r[4], uint32_t addr) {
    asm volatile("ldmatrix.sync.aligned.m8n8.x4.shared.b16 {%0,%1,%2,%3}, [%4];"
        : "=r"(r[0]), "=r"(r[1]), "=r"(r[2]), "=r"(r[3]) : "r"(addr));
}

__device__ __forceinline__ void mma_f16(float d[4], const uint32_t a[4],
                                        uint32_t b0, uint32_t b1) {
    asm volatile(
        "mma.sync.aligned.m16n8k16.row.col.f32.f16.f16.f32 "
        "{%0,%1,%2,%3}, {%4,%5,%6,%7}, {%8,%9}, {%0,%1,%2,%3};"
        : "+f"(d[0]), "+f"(d[1]), "+f"(d[2]), "+f"(d[3])
        : "r"(a[0]), "r"(a[1]), "r"(a[2]), "r"(a[3]), "r"(b0), "r"(b1));
}

// ---------------------------------------------------------------------------
// K0: styles (blocks 0..47) + weight-pack-with-wsq (blocks 48..2095)
// ---------------------------------------------------------------------------
#define K0_BLOCKS (48 + 2048)
__global__ void prep1_kernel(const float* __restrict__ w,
                             const float* __restrict__ m1w, const float* __restrict__ m1b,
                             const float* __restrict__ m2w, const float* __restrict__ m2b,
                             const float* __restrict__ mrw, const float* __restrict__ mrb,
                             const float* __restrict__ w1, const float* __restrict__ w2)
{
    if (blockIdx.x < 48) {
        int idx = blockIdx.x * 256 + threadIdx.x;     // 0..12287
        int sel = idx >> 12;
        int r = idx & 4095;
        const float* mw = (sel == 0) ? m1w : (sel == 1) ? m2w : mrw;
        const float* mb = (sel == 0) ? m1b : (sel == 1) ? m2b : mrb;
        float* outp = (sel == 0) ? g_s1 : (sel == 1) ? g_s2 : g_sr;
        int b = r >> 9, c = r & 511;
        const float* wb = w + (size_t)b * CH;
        const float* mwc = mw + (size_t)c * CH;
        float acc = mb[c];
        #pragma unroll 8
        for (int t = 0; t < CH; t++) acc += wb[t] * mwc[t];
        outp[r] = acc;
        return;
    }
    // wpack + wsq: thread per (which, co*512+ci)
    int idx = (blockIdx.x - 48) * 256 + threadIdx.x;  // 0..524287
    int which = idx >> 18;
    int e = idx & 262143;                             // co*512 + ci
    const float* wgt = which ? w2 : w1;
    __half* out = which ? g_w2p : g_w1p;
    const float* p = wgt + (size_t)e * 9;
    float q = 0.f;
    #pragma unroll
    for (int tap = 0; tap < 9; tap++) {
        float v = p[tap];
        q += v * v;
        out[(size_t)tap * (CH * CH) + e] = __float2half(v);
    }
    g_wsq[which][e] = q;
}

// ---------------------------------------------------------------------------
// K1: demod (blocks 0..8191) + upsample/border (blocks 8192..12351)
// ---------------------------------------------------------------------------
#define K1_BLOCKS (8192 + 4160)
__global__ void prep2_kernel(const float* __restrict__ x)
{
    if (blockIdx.x < 8192) {
        // demod: one block per (which, b, co); reads wsq row (2KB) + style row
        __shared__ float red[256];
        const int which = blockIdx.x >> 12;
        const int bc = blockIdx.x & 4095;
        const int b  = bc >> 9;
        const int co = bc & 511;
        const int t  = threadIdx.x;
        const float* qrow = g_wsq[which] + (size_t)co * CH;
        const float* s = which ? g_s2 : g_s1;
        float* d       = which ? g_d2 : g_d1;
        float partial = 0.f;
        #pragma unroll
        for (int h = 0; h < 2; h++) {
            int ci = t + h * 256;
            float sv = s[b * CH + ci];
            partial += qrow[ci] * sv * sv;
        }
        red[t] = partial;
        __syncthreads();
        for (int off = 128; off >= 32; off >>= 1) {
            if (t < off) red[t] += red[t + off];
            __syncthreads();
        }
        if (t < 32) {
            float v = red[t];
            #pragma unroll
            for (int off = 16; off > 0; off >>= 1)
                v += __shfl_down_sync(0xffffffffu, v, off);
            if (t == 0) d[b * CH + co] = rsqrtf(v + 1e-8f);
        }
        return;
    }

    // upsample / border-zero
    __shared__ float rows[64][2][33];
    int u = blockIdx.x - 8192;            // 0..4159
    int b  = u / 520;
    int r  = u - b * 520;
    int y  = r >> 3;                      // 0..64
    int c0 = (r & 7) * 64;

    if (y == 64) {
        for (int i = (r & 7) * 256 + threadIdx.x; i < 260 * 64; i += 8 * 256) {
            int uu = i & 63;
            int bp = i >> 6;
            int row, col;
            if (bp < 66)       { row = 0;  col = bp; }
            else if (bp < 132) { row = 65; col = bp - 66; }
            else { int j = bp - 132; row = 1 + (j >> 1); col = (j & 1) ? 65 : 0; }
            size_t off = (((size_t)(b * HP + row)) * WP + col) * CPX;
            uint4 z = make_uint4(0, 0, 0, 0);
            ((uint4*)(g_a1 + off))[uu] = z;
            ((uint4*)(g_a2 + off))[uu] = z;
        }
        return;
    }

    float syf = y * 0.5f - 0.25f;
    int y0i = (int)floorf(syf);
    float fy = syf - (float)y0i;
    int ya = max(y0i, 0), yb = min(y0i + 1, HI - 1);
    for (int i = threadIdx.x; i < 64 * 2 * 32; i += 256) {
        int ci = i >> 6, rr = (i >> 5) & 1, xx = i & 31;
        rows[ci][rr][xx] = x[(((size_t)(b * CH + c0 + ci)) * HI + (rr ? yb : ya)) * WI + xx];
    }
    __syncthreads();
    int px = threadIdx.x >> 2;
    int g  = (threadIdx.x & 3) * 16;
    float sxf = px * 0.5f - 0.25f;
    int x0i = (int)floorf(sxf);
    float fx = sxf - (float)x0i;
    int xa = max(x0i, 0), xb = min(x0i + 1, WI - 1);
    size_t obase = (((size_t)(b * HP + y + 1)) * WP + (px + 1)) * CPX + c0 + g;

    uint32_t hbuf[8];
    #pragma unroll
    for (int j2 = 0; j2 < 8; j2++) {
        float vv[2];
        #pragma unroll
        for (int e = 0; e < 2; e++) {
            int ci = g + j2 * 2 + e;
            float v0 = rows[ci][0][xa] * (1.f - fx) + rows[ci][0][xb] * fx;
            float v1 = rows[ci][1][xa] * (1.f - fx) + rows[ci][1][xb] * fx;
            vv[e] = (v0 * (1.f - fy) + v1 * fy) * g_s1[b * CH + c0 + ci];
        }
        hbuf[j2] = pack_f16x2(__float2half(vv[0]), __float2half(vv[1]));
    }
    uint4* oh = (uint4*)(g_a1 + obase);
    oh[0] = make_uint4(hbuf[0], hbuf[1], hbuf[2], hbuf[3]);
    oh[1] = make_uint4(hbuf[4], hbuf[5], hbuf[6], hbuf[7]);
}

// ---------------------------------------------------------------------------
// Convs: mma.sync implicit-GEMM conv3x3, plain fp16, fp32 acc.
// Block 256 thr (8 warps, 2M x 4N). Tile M=128 px, N=128 co, BK=64.
// Stage 32KB, 3 stages = 96KB => 2 CTAs/SM; distance-2 issue; loop unroll x3
// with compile-time stage offsets.
// ---------------------------------------------------------------------------
#define STAGE 32768
#define NSTAGE 3
#define DSMEM (NSTAGE*STAGE)
#define NITER 72            // 9 taps x 8 ci-chunks of 64 (divisible by 3)

template<int PHASE>
__global__ void __launch_bounds__(256, 2)
conv_mma_kernel(const __half* __restrict__ aIn,
                const __half* __restrict__ wp,
                const float* __restrict__ dmod,
                const float* __restrict__ nscale,
                const float* __restrict__ noise,
                const float* __restrict__ s2,
                __half* __restrict__ outA,
                float* __restrict__ h_out)
{
    extern __shared__ __align__(128) char dsm[];
    __shared__ float e_d[128], e_ns[128], e_s2[128];

    const int tid = threadIdx.x;
    const int lane = tid & 31;
    const int wid = tid >> 5;
    const int warp_m = wid & 1;
    const int warp_n = wid >> 1;
    const int co0 = blockIdx.x * 128;
    const int y0  = blockIdx.y * 2;
    const int b   = blockIdx.z;

    const uint32_t sb = smem_u32(dsm);

    if (tid < 128) {
        e_d[tid]  = dmod[b * CH + co0 + tid];
        e_ns[tid] = nscale[co0 + tid];
        e_s2[tid] = (PHASE == 1) ? s2[b * CH + co0 + tid] : 0.f;
    }

    float acc[4][4][4] = {};

    // affine cp.async bases
    const int r0  = tid >> 3;
    const int col = tid & 7;
    const uint32_t baseAoff =
        (uint32_t)(((b * HP + y0) * WP + r0) * CPX + (col << 3));
    const uint32_t baseBoff =
        (uint32_t)(((co0 + r0) << 9) + (col << 3));
    const uint32_t dstA0 = (uint32_t)(r0 * 128 + ((col ^ (r0 & 7)) << 4));
    const uint32_t dstB0 = dstA0 + 16384u;
    const uint32_t AOFF1 = 32u * CPX;
    const uint32_t AOFF2 = (uint32_t)WP * CPX;

    auto issue = [&](int it, uint32_t bufOff) {
        const int tap = it >> 3;
        const int ci0 = (it & 7) << 6;
        const int dy = (tap * 171) >> 9;
        const int dx = tap - dy * 3;
        const __half* ga = aIn + baseAoff + (uint32_t)((dy * WP + dx) * CPX + ci0);
        const __half* gb = wp + baseBoff + (uint32_t)(tap * (CH * CH) + ci0);
        const uint32_t dA = sb + bufOff + dstA0;
        const uint32_t dB = sb + bufOff + dstB0;
        #pragma unroll
        for (int rep = 0; rep < 4; rep++) {
            const uint32_t ao = (rep & 1 ? AOFF1 : 0u) + (rep >> 1 ? AOFF2 : 0u);
            CP_ASYNC16(dA + rep * 4096, ga + ao);
            CP_ASYNC16(dB + rep * 4096, gb + rep * 16384);
        }
        CP_COMMIT();
    };

    issue(0, 0);
    issue(1, STAGE);

    // loop-invariant ldsm row bases
    const int laneHi = lane >> 4;
    uint32_t rowA[4], rsA[4], rowB[2], rsB[2];
    #pragma unroll
    for (int mt = 0; mt < 4; mt++) {
        int row = warp_m * 64 + mt * 16 + (lane & 15);
        rowA[mt] = (uint32_t)(row * 128);
        rsA[mt]  = (uint32_t)(row & 7);
    }
    #pragma unroll
    for (int nt = 0; nt < 2; nt++) {
        int row = warp_n * 32 + nt * 16 + (lane & 15);
        rowB[nt] = (uint32_t)(16384 + row * 128);
        rsB[nt]  = (uint32_t)(row & 7);
    }

    auto step = [&](int it, uint32_t curOff, uint32_t nxtOff) {
        CP_WAIT(1);
        __syncthreads();
        const uint32_t S = sb + curOff;
        #pragma unroll
        for (int ks = 0; ks < 4; ks++) {
            const uint32_t colA = (uint32_t)(ks * 2 + laneHi);
            uint32_t ah[4][4], bh[2][4];
            #pragma unroll
            for (int mt = 0; mt < 4; mt++)
                ldsm_x4(ah[mt], S + rowA[mt] + ((colA ^ rsA[mt]) << 4));
            #pragma unroll
            for (int nt = 0; nt < 2; nt++)
                ldsm_x4(bh[nt], S + rowB[nt] + ((colA ^ rsB[nt]) << 4));
            #pragma unroll
            for (int mt = 0; mt < 4; mt++)
                #pragma unroll
                for (int nt = 0; nt < 2; nt++)
                    #pragma unroll
                    for (int hf = 0; hf < 2; hf++)
                        mma_f16(acc[mt][nt * 2 + hf], ah[mt],
                                bh[nt][hf], bh[nt][hf + 2]);
            if (ks == 0 && it + 2 < NITER) issue(it + 2, nxtOff);
        }
    };

    #pragma unroll 1
    for (int it = 0; it < NITER; it += 3) {
        step(it,     0,         2 * STAGE);
        step(it + 1, STAGE,     0);
        step(it + 2, 2 * STAGE, STAGE);
    }

    // epilogue
    #pragma unroll
    for (int mt = 0; mt < 4; mt++) {
        #pragma unroll
        for (int rr = 0; rr < 2; rr++) {
            int m = warp_m * 64 + mt * 16 + rr * 8 + (lane >> 2);
            int py = y0 + (m >> 6);
            int px = m & 63;
            float nz = noise[(size_t)b * PLANE_O + py * WO + px];
            #pragma unroll
            for (int nj = 0; nj < 4; nj++) {
                int nrel = warp_n * 32 + nj * 8 + (lane & 3) * 2;
                float v0 = acc[mt][nj][rr * 2 + 0] * e_d[nrel]     + e_ns[nrel]     * nz;
                float v1 = acc[mt][nj][rr * 2 + 1] * e_d[nrel + 1] + e_ns[nrel + 1] * nz;
                v0 = (v0 >= 0.f) ? v0 : 0.2f * v0;
                v1 = (v1 >= 0.f) ? v1 : 0.2f * v1;
                if (PHASE == 1) {
                    v0 *= e_s2[nrel];
                    v1 *= e_s2[nrel + 1];
                    size_t o = ((((size_t)b * HP + py + 1) * WP) + px + 1) * CPX + co0 + nrel;
                    *(uint32_t*)(outA + o) = pack_f16x2(__float2half(v0), __float2half(v1));
                } else {
                    size_t o = ((size_t)b * CH + co0 + nrel) * PLANE_O + py * WO + px;
                    h_out[o] = v0;
                    h_out[o + PLANE_O] = v1;
                }
            }
        }
    }
}

// ---------------------------------------------------------------------------
// K4: to-RGB 1x1 conv
// ---------------------------------------------------------------------------
__global__ void rgb_kernel(const float* __restrict__ h, const float* __restrict__ rgbw,
                           float* __restrict__ rgb)
{
    __shared__ float weff[3 * CH];
    int b = blockIdx.y;
    for (int i = threadIdx.x; i < 3 * CH; i += 256) {
        int c = i / CH, ci = i % CH;
        weff[i] = rgbw[c * CH + ci] * g_sr[b * CH + ci];
    }
    __syncthreads();
    int pix = blockIdx.x * 256 + threadIdx.x;
    const float* hb = h + (size_t)b * CH * PLANE_O + pix;
    float a0 = 0.f, a1 = 0.f, a2 = 0.f;
    #pragma unroll 4
    for (int ci = 0; ci < CH; ci++) {
        float hv = hb[(size_t)ci * PLANE_O];
        a0 += weff[ci] * hv;
        a1 += weff[CH + ci] * hv;
        a2 += weff[2 * CH + ci] * hv;
    }
    float* rb = rgb + (size_t)b * 3 * PLANE_O + pix;
    rb[0] = a0; rb[PLANE_O] = a1; rb[2 * PLANE_O] = a2;
}

// ---------------------------------------------------------------------------
// host launch
// ---------------------------------------------------------------------------
extern "C" void kernel_launch(void* const* d_in, const int* in_sizes, int n_in,
                              void* d_out, int out_size)
{
    const float* x   = (const float*)d_in[0];
    const float* w   = (const float*)d_in[1];
    const float* w1  = (const float*)d_in[2];
    const float* m1w = (const float*)d_in[3];
    const float* m1b = (const float*)d_in[4];
    const float* ns1 = (const float*)d_in[5];
    const float* w2  = (const float*)d_in[6];
    const float* m2w = (const float*)d_in[7];
    const float* m2b = (const float*)d_in[8];
    const float* ns2 = (const float*)d_in[9];
    const float* wr  = (const float*)d_in[10];
    const float* mrw = (const float*)d_in[11];
    const float* mrb = (const float*)d_in[12];
    const float* n1  = (const float*)d_in[13];
    const float* n2  = (const float*)d_in[14];

    float* out     = (float*)d_out;
    float* h_out   = out;                                  // [8,512,64,64]
    float* rgb_out = out + (size_t)BATCH * CH * PLANE_O;   // [8,3,64,64]

    float *p_s2, *p_d1, *p_d2;
    __half *p_a1, *p_a2, *p_w1p, *p_w2p;
    cudaGetSymbolAddress((void**)&p_s2, g_s2);
    cudaGetSymbolAddress((void**)&p_d1, g_d1);
    cudaGetSymbolAddress((void**)&p_d2, g_d2);
    cudaGetSymbolAddress((void**)&p_a1, g_a1);
    cudaGetSymbolAddress((void**)&p_a2, g_a2);
    cudaGetSymbolAddress((void**)&p_w1p, g_w1p);
    cudaGetSymbolAddress((void**)&p_w2p, g_w2p);

    cudaFuncSetAttribute(conv_mma_kernel<1>, cudaFuncAttributeMaxDynamicSharedMemorySize, DSMEM);
    cudaFuncSetAttribute(conv_mma_kernel<2>, cudaFuncAttributeMaxDynamicSharedMemorySize, DSMEM);

    // K0: styles + weight-pack(+wsq)
    prep1_kernel<<<K0_BLOCKS, 256>>>(w, m1w, m1b, m2w, m2b, mrw, mrb, w1, w2);
    // K1: demod + upsample + border zero
    prep2_kernel<<<K1_BLOCKS, 256>>>(x);
    // K2: conv1 (a1 -> a2, pre-modulated by s2)
    {
        dim3 g(4, 32, 8);
        conv_mma_kernel<1><<<g, 256, DSMEM>>>(p_a1, p_w1p, p_d1, ns1, n1,
                                              p_s2, p_a2, nullptr);
    }
    // K3: conv2 (a2 -> h_out fp32)
    {
        dim3 g(4, 32, 8);
        conv_mma_kernel<2><<<g, 256, DSMEM>>>(p_a2, p_w2p, p_d2, ns2, n2,
                                              nullptr, nullptr, h_out);
    }
    // K4: rgb
    {
        dim3 g(PLANE_O / 256, BATCH);
        rgb_kernel<<<g, 256>>>(h_out, wr, rgb_out);
    }
    (void)in_sizes; (void)n_in; (void)out_size;
}

// round 16
// speedup vs baseline: 2.9585x; 1.0912x over previous
#include <cuda_runtime.h>
#include <cuda_fp16.h>
#include <math.h>
#include <stdint.h>

// ---------------------------------------------------------------------------
// Problem dims (fixed)
// ---------------------------------------------------------------------------
#define BATCH 8
#define CH    512
#define HI    32
#define WI    32
#define HO    64
#define WO    64
#define HP    66
#define WP    66
#define PLANE_O (HO*WO)          // 4096
#define CPX   512                // fp16 channels per pixel

// ---------------------------------------------------------------------------
// Static device scratch (no allocations allowed)
// ---------------------------------------------------------------------------
__device__ __half g_a1[(size_t)BATCH*HP*WP*CPX];
__device__ __half g_a2[(size_t)BATCH*HP*WP*CPX];
__device__ __half g_w1p[9LL*CH*CH];
__device__ __half g_w2p[9LL*CH*CH];
__device__ float g_wsq[2][CH*CH];       // sum_tap w^2 per (co,ci)
__device__ float g_s1[BATCH*CH];
__device__ float g_s2[BATCH*CH];
__device__ float g_sr[BATCH*CH];
__device__ float g_d1[BATCH*CH];
__device__ float g_d2[BATCH*CH];

// ---------------------------------------------------------------------------
// PTX helpers
// ---------------------------------------------------------------------------
__device__ __forceinline__ uint32_t smem_u32(const void* p) {
    uint32_t a;
    asm("{ .reg .u64 t; cvta.to.shared.u64 t, %1; cvt.u32.u64 %0, t; }"
        : "=r"(a) : "l"(p));
    return a;
}

__device__ __forceinline__ uint32_t pack_f16x2(__half lo, __half hi) {
    return (uint32_t)__half_as_ushort(lo) | ((uint32_t)__half_as_ushort(hi) << 16);
}

#define CP_ASYNC16(dst, src) \
    asm volatile("cp.async.cg.shared.global [%0], [%1], 16;" \
        :: "r"(dst), "l"(src) : "memory")
#define CP_COMMIT() asm volatile("cp.async.commit_group;" ::: "memory")
#define CP_WAIT(N)  asm volatile("cp.async.wait_group %0;" :: "n"(N) : "memory")

__device__ __forceinline__ void ldsm_x4(uint32_t r[4], uint32_t addr) {
    asm volatile("ldmatrix.sync.aligned.m8n8.x4.shared.b16 {%0,%1,%2,%3}, [%4];"
        : "=r"(r[0]), "=r"(r[1]), "=r"(r[2]), "=r"(r[3]) : "r"(addr));
}

__device__ __forceinline__ void mma_f16(float d[4], const uint32_t a[4],
                                        uint32_t b0, uint32_t b1) {
    asm volatile(
        "mma.sync.aligned.m16n8k16.row.col.f32.f16.f16.f32 "
        "{%0,%1,%2,%3}, {%4,%5,%6,%7}, {%8,%9}, {%0,%1,%2,%3};"
        : "+f"(d[0]), "+f"(d[1]), "+f"(d[2]), "+f"(d[3])
        : "r"(a[0]), "r"(a[1]), "r"(a[2]), "r"(a[3]), "r"(b0), "r"(b1));
}

// ---------------------------------------------------------------------------
// K0: styles (blocks 0..47) + weight-pack-with-wsq (blocks 48..2095)
// ---------------------------------------------------------------------------
#define K0_BLOCKS (48 + 2048)
__global__ void prep1_kernel(const float* __restrict__ w,
                             const float* __restrict__ m1w, const float* __restrict__ m1b,
                             const float* __restrict__ m2w, const float* __restrict__ m2b,
                             const float* __restrict__ mrw, const float* __restrict__ mrb,
                             const float* __restrict__ w1, const float* __restrict__ w2)
{
    if (blockIdx.x < 48) {
        int idx = blockIdx.x * 256 + threadIdx.x;
        int sel = idx >> 12;
        int r = idx & 4095;
        const float* mw = (sel == 0) ? m1w : (sel == 1) ? m2w : mrw;
        const float* mb = (sel == 0) ? m1b : (sel == 1) ? m2b : mrb;
        float* outp = (sel == 0) ? g_s1 : (sel == 1) ? g_s2 : g_sr;
        int b = r >> 9, c = r & 511;
        const float* wb = w + (size_t)b * CH;
        const float* mwc = mw + (size_t)c * CH;
        float acc = mb[c];
        #pragma unroll 8
        for (int t = 0; t < CH; t++) acc += wb[t] * mwc[t];
        outp[r] = acc;
        return;
    }
    int idx = (blockIdx.x - 48) * 256 + threadIdx.x;
    int which = idx >> 18;
    int e = idx & 262143;
    const float* wgt = which ? w2 : w1;
    __half* out = which ? g_w2p : g_w1p;
    const float* p = wgt + (size_t)e * 9;
    float q = 0.f;
    #pragma unroll
    for (int tap = 0; tap < 9; tap++) {
        float v = p[tap];
        q += v * v;
        out[(size_t)tap * (CH * CH) + e] = __float2half(v);
    }
    g_wsq[which][e] = q;
}

// ---------------------------------------------------------------------------
// K1: demod (0..8191) + upsample/border (8192..12351) + rgb-zero (12352..12447)
// ---------------------------------------------------------------------------
#define K1_BLOCKS (8192 + 4160 + 96)
__global__ void prep2_kernel(const float* __restrict__ x, float* __restrict__ rgb_out)
{
    if (blockIdx.x >= 8192 + 4160) {
        int u = (blockIdx.x - (8192 + 4160)) * 256 + threadIdx.x;  // 0..24575
        ((uint4*)rgb_out)[u] = make_uint4(0, 0, 0, 0);
        return;
    }
    if (blockIdx.x < 8192) {
        __shared__ float red[256];
        const int which = blockIdx.x >> 12;
        const int bc = blockIdx.x & 4095;
        const int b  = bc >> 9;
        const int co = bc & 511;
        const int t  = threadIdx.x;
        const float* qrow = g_wsq[which] + (size_t)co * CH;
        const float* s = which ? g_s2 : g_s1;
        float* d       = which ? g_d2 : g_d1;
        float partial = 0.f;
        #pragma unroll
        for (int h = 0; h < 2; h++) {
            int ci = t + h * 256;
            float sv = s[b * CH + ci];
            partial += qrow[ci] * sv * sv;
        }
        red[t] = partial;
        __syncthreads();
        for (int off = 128; off >= 32; off >>= 1) {
            if (t < off) red[t] += red[t + off];
            __syncthreads();
        }
        if (t < 32) {
            float v = red[t];
            #pragma unroll
            for (int off = 16; off > 0; off >>= 1)
                v += __shfl_down_sync(0xffffffffu, v, off);
            if (t == 0) d[b * CH + co] = rsqrtf(v + 1e-8f);
        }
        return;
    }

    __shared__ float rows[64][2][33];
    int u = blockIdx.x - 8192;
    int b  = u / 520;
    int r  = u - b * 520;
    int y  = r >> 3;
    int c0 = (r & 7) * 64;

    if (y == 64) {
        for (int i = (r & 7) * 256 + threadIdx.x; i < 260 * 64; i += 8 * 256) {
            int uu = i & 63;
            int bp = i >> 6;
            int row, col;
            if (bp < 66)       { row = 0;  col = bp; }
            else if (bp < 132) { row = 65; col = bp - 66; }
            else { int j = bp - 132; row = 1 + (j >> 1); col = (j & 1) ? 65 : 0; }
            size_t off = (((size_t)(b * HP + row)) * WP + col) * CPX;
            uint4 z = make_uint4(0, 0, 0, 0);
            ((uint4*)(g_a1 + off))[uu] = z;
            ((uint4*)(g_a2 + off))[uu] = z;
        }
        return;
    }

    float syf = y * 0.5f - 0.25f;
    int y0i = (int)floorf(syf);
    float fy = syf - (float)y0i;
    int ya = max(y0i, 0), yb = min(y0i + 1, HI - 1);
    for (int i = threadIdx.x; i < 64 * 2 * 32; i += 256) {
        int ci = i >> 6, rr = (i >> 5) & 1, xx = i & 31;
        rows[ci][rr][xx] = x[(((size_t)(b * CH + c0 + ci)) * HI + (rr ? yb : ya)) * WI + xx];
    }
    __syncthreads();
    int px = threadIdx.x >> 2;
    int g  = (threadIdx.x & 3) * 16;
    float sxf = px * 0.5f - 0.25f;
    int x0i = (int)floorf(sxf);
    float fx = sxf - (float)x0i;
    int xa = max(x0i, 0), xb = min(x0i + 1, WI - 1);
    size_t obase = (((size_t)(b * HP + y + 1)) * WP + (px + 1)) * CPX + c0 + g;

    uint32_t hbuf[8];
    #pragma unroll
    for (int j2 = 0; j2 < 8; j2++) {
        float vv[2];
        #pragma unroll
        for (int e = 0; e < 2; e++) {
            int ci = g + j2 * 2 + e;
            float v0 = rows[ci][0][xa] * (1.f - fx) + rows[ci][0][xb] * fx;
            float v1 = rows[ci][1][xa] * (1.f - fx) + rows[ci][1][xb] * fx;
            vv[e] = (v0 * (1.f - fy) + v1 * fy) * g_s1[b * CH + c0 + ci];
        }
        hbuf[j2] = pack_f16x2(__float2half(vv[0]), __float2half(vv[1]));
    }
    uint4* oh = (uint4*)(g_a1 + obase);
    oh[0] = make_uint4(hbuf[0], hbuf[1], hbuf[2], hbuf[3]);
    oh[1] = make_uint4(hbuf[4], hbuf[5], hbuf[6], hbuf[7]);
}

// ---------------------------------------------------------------------------
// Convs: mma.sync implicit-GEMM conv3x3, plain fp16, fp32 acc.
// Tile M=128 px, N=128 co, BK=64; 3 stages x 32KB => 2 CTAs/SM; distance-2.
// cp.async burst issued at ks==3 (off the post-barrier critical path).
// PHASE 2 additionally accumulates the to-RGB 1x1 conv via lane reduction +
// global atomicAdd (rgb_out pre-zeroed by prep2).
// ---------------------------------------------------------------------------
#define STAGE 32768
#define NSTAGE 3
#define DSMEM (NSTAGE*STAGE)
#define NITER 72

template<int PHASE>
__global__ void __launch_bounds__(256, 2)
conv_mma_kernel(const __half* __restrict__ aIn,
                const __half* __restrict__ wp,
                const float* __restrict__ dmod,
                const float* __restrict__ nscale,
                const float* __restrict__ noise,
                const float* __restrict__ sAux,   // PHASE1: s2 ; PHASE2: sr
                const float* __restrict__ rgbw,   // PHASE2 only
                __half* __restrict__ outA,        // PHASE1
                float* __restrict__ h_out,        // PHASE2
                float* __restrict__ rgb_out)      // PHASE2
{
    extern __shared__ __align__(128) char dsm[];
    __shared__ float e_d[128], e_ns[128], e_s2[128];
    __shared__ float e_wr[3][128];

    const int tid = threadIdx.x;
    const int lane = tid & 31;
    const int wid = tid >> 5;
    const int warp_m = wid & 1;
    const int warp_n = wid >> 1;
    const int co0 = blockIdx.x * 128;
    const int y0  = blockIdx.y * 2;
    const int b   = blockIdx.z;

    const uint32_t sb = smem_u32(dsm);

    if (tid < 128) {
        e_d[tid]  = dmod[b * CH + co0 + tid];
        e_ns[tid] = nscale[co0 + tid];
        if (PHASE == 1) {
            e_s2[tid] = sAux[b * CH + co0 + tid];
        } else {
            float sr = sAux[b * CH + co0 + tid];
            #pragma unroll
            for (int c = 0; c < 3; c++)
                e_wr[c][tid] = rgbw[c * CH + co0 + tid] * sr;
        }
    }

    float acc[4][4][4] = {};

    const int r0  = tid >> 3;
    const int col = tid & 7;
    const uint32_t baseAoff =
        (uint32_t)(((b * HP + y0) * WP + r0) * CPX + (col << 3));
    const uint32_t baseBoff =
        (uint32_t)(((co0 + r0) << 9) + (col << 3));
    const uint32_t dstA0 = (uint32_t)(r0 * 128 + ((col ^ (r0 & 7)) << 4));
    const uint32_t dstB0 = dstA0 + 16384u;
    const uint32_t AOFF1 = 32u * CPX;
    const uint32_t AOFF2 = (uint32_t)WP * CPX;

    auto issue = [&](int it, uint32_t bufOff) {
        const int tap = it >> 3;
        const int ci0 = (it & 7) << 6;
        const int dy = (tap * 171) >> 9;
        const int dx = tap - dy * 3;
        const __half* ga = aIn + baseAoff + (uint32_t)((dy * WP + dx) * CPX + ci0);
        const __half* gb = wp + baseBoff + (uint32_t)(tap * (CH * CH) + ci0);
        const uint32_t dA = sb + bufOff + dstA0;
        const uint32_t dB = sb + bufOff + dstB0;
        #pragma unroll
        for (int rep = 0; rep < 4; rep++) {
            const uint32_t ao = (rep & 1 ? AOFF1 : 0u) + (rep >> 1 ? AOFF2 : 0u);
            CP_ASYNC16(dA + rep * 4096, ga + ao);
            CP_ASYNC16(dB + rep * 4096, gb + rep * 16384);
        }
        CP_COMMIT();
    };

    issue(0, 0);
    issue(1, STAGE);

    const int laneHi = lane >> 4;
    uint32_t rowA[4], rsA[4], rowB[2], rsB[2];
    #pragma unroll
    for (int mt = 0; mt < 4; mt++) {
        int row = warp_m * 64 + mt * 16 + (lane & 15);
        rowA[mt] = (uint32_t)(row * 128);
        rsA[mt]  = (uint32_t)(row & 7);
    }
    #pragma unroll
    for (int nt = 0; nt < 2; nt++) {
        int row = warp_n * 32 + nt * 16 + (lane & 15);
        rowB[nt] = (uint32_t)(16384 + row * 128);
        rsB[nt]  = (uint32_t)(row & 7);
    }

    auto step = [&](int it, uint32_t curOff, uint32_t nxtOff) {
        CP_WAIT(1);
        __syncthreads();
        const uint32_t S = sb + curOff;
        #pragma unroll
        for (int ks = 0; ks < 4; ks++) {
            const uint32_t colA = (uint32_t)(ks * 2 + laneHi);
            uint32_t ah[4][4], bh[2][4];
            #pragma unroll
            for (int mt = 0; mt < 4; mt++)
                ldsm_x4(ah[mt], S + rowA[mt] + ((colA ^ rsA[mt]) << 4));
            #pragma unroll
            for (int nt = 0; nt < 2; nt++)
                ldsm_x4(bh[nt], S + rowB[nt] + ((colA ^ rsB[nt]) << 4));
            #pragma unroll
            for (int mt = 0; mt < 4; mt++)
                #pragma unroll
                for (int nt = 0; nt < 2; nt++)
                    #pragma unroll
                    for (int hf = 0; hf < 2; hf++)
                        mma_f16(acc[mt][nt * 2 + hf], ah[mt],
                                bh[nt][hf], bh[nt][hf + 2]);
            if (ks == 3 && it + 2 < NITER) issue(it + 2, nxtOff);
        }
    };

    #pragma unroll 1
    for (int it = 0; it < NITER; it += 3) {
        step(it,     0,         2 * STAGE);
        step(it + 1, STAGE,     0);
        step(it + 2, 2 * STAGE, STAGE);
    }

    // epilogue
    #pragma unroll
    for (int mt = 0; mt < 4; mt++) {
        #pragma unroll
        for (int rr = 0; rr < 2; rr++) {
            int m = warp_m * 64 + mt * 16 + rr * 8 + (lane >> 2);
            int py = y0 + (m >> 6);
            int px = m & 63;
            float nz = noise[(size_t)b * PLANE_O + py * WO + px];
            float rc0 = 0.f, rc1 = 0.f, rc2 = 0.f;
            #pragma unroll
            for (int nj = 0; nj < 4; nj++) {
                int nrel = warp_n * 32 + nj * 8 + (lane & 3) * 2;
                float v0 = acc[mt][nj][rr * 2 + 0] * e_d[nrel]     + e_ns[nrel]     * nz;
                float v1 = acc[mt][nj][rr * 2 + 1] * e_d[nrel + 1] + e_ns[nrel + 1] * nz;
                v0 = (v0 >= 0.f) ? v0 : 0.2f * v0;
                v1 = (v1 >= 0.f) ? v1 : 0.2f * v1;
                if (PHASE == 1) {
                    v0 *= e_s2[nrel];
                    v1 *= e_s2[nrel + 1];
                    size_t o = ((((size_t)b * HP + py + 1) * WP) + px + 1) * CPX + co0 + nrel;
                    *(uint32_t*)(outA + o) = pack_f16x2(__float2half(v0), __float2half(v1));
                } else {
                    size_t o = ((size_t)b * CH + co0 + nrel) * PLANE_O + py * WO + px;
                    h_out[o] = v0;
                    h_out[o + PLANE_O] = v1;
                    rc0 += e_wr[0][nrel] * v0 + e_wr[0][nrel + 1] * v1;
                    rc1 += e_wr[1][nrel] * v0 + e_wr[1][nrel + 1] * v1;
                    rc2 += e_wr[2][nrel] * v0 + e_wr[2][nrel + 1] * v1;
                }
            }
            if (PHASE == 2) {
                // reduce over the 4 lanes (lane&3) sharing this pixel
                rc0 += __shfl_xor_sync(0xffffffffu, rc0, 1);
                rc0 += __shfl_xor_sync(0xffffffffu, rc0, 2);
                rc1 += __shfl_xor_sync(0xffffffffu, rc1, 1);
                rc1 += __shfl_xor_sync(0xffffffffu, rc1, 2);
                rc2 += __shfl_xor_sync(0xffffffffu, rc2, 1);
                rc2 += __shfl_xor_sync(0xffffffffu, rc2, 2);
                int lc = lane & 3;
                if (lc < 3) {
                    float rv = (lc == 0) ? rc0 : (lc == 1) ? rc1 : rc2;
                    atomicAdd(rgb_out + (size_t)b * 3 * PLANE_O + lc * PLANE_O
                              + py * WO + px, rv);
                }
            }
        }
    }
}

// ---------------------------------------------------------------------------
// host launch
// ---------------------------------------------------------------------------
extern "C" void kernel_launch(void* const* d_in, const int* in_sizes, int n_in,
                              void* d_out, int out_size)
{
    const float* x   = (const float*)d_in[0];
    const float* w   = (const float*)d_in[1];
    const float* w1  = (const float*)d_in[2];
    const float* m1w = (const float*)d_in[3];
    const float* m1b = (const float*)d_in[4];
    const float* ns1 = (const float*)d_in[5];
    const float* w2  = (const float*)d_in[6];
    const float* m2w = (const float*)d_in[7];
    const float* m2b = (const float*)d_in[8];
    const float* ns2 = (const float*)d_in[9];
    const float* wr  = (const float*)d_in[10];
    const float* mrw = (const float*)d_in[11];
    const float* mrb = (const float*)d_in[12];
    const float* n1  = (const float*)d_in[13];
    const float* n2  = (const float*)d_in[14];

    float* out     = (float*)d_out;
    float* h_out   = out;                                  // [8,512,64,64]
    float* rgb_out = out + (size_t)BATCH * CH * PLANE_O;   // [8,3,64,64]

    float *p_s2, *p_sr, *p_d1, *p_d2;
    __half *p_a1, *p_a2, *p_w1p, *p_w2p;
    cudaGetSymbolAddress((void**)&p_s2, g_s2);
    cudaGetSymbolAddress((void**)&p_sr, g_sr);
    cudaGetSymbolAddress((void**)&p_d1, g_d1);
    cudaGetSymbolAddress((void**)&p_d2, g_d2);
    cudaGetSymbolAddress((void**)&p_a1, g_a1);
    cudaGetSymbolAddress((void**)&p_a2, g_a2);
    cudaGetSymbolAddress((void**)&p_w1p, g_w1p);
    cudaGetSymbolAddress((void**)&p_w2p, g_w2p);

    cudaFuncSetAttribute(conv_mma_kernel<1>, cudaFuncAttributeMaxDynamicSharedMemorySize, DSMEM);
    cudaFuncSetAttribute(conv_mma_kernel<2>, cudaFuncAttributeMaxDynamicSharedMemorySize, DSMEM);

    // K0: styles + weight-pack(+wsq)
    prep1_kernel<<<K0_BLOCKS, 256>>>(w, m1w, m1b, m2w, m2b, mrw, mrb, w1, w2);
    // K1: demod + upsample + border zero + rgb zero
    prep2_kernel<<<K1_BLOCKS, 256>>>(x, rgb_out);
    // K2: conv1 (a1 -> a2, pre-modulated by s2)
    {
        dim3 g(4, 32, 8);
        conv_mma_kernel<1><<<g, 256, DSMEM>>>(p_a1, p_w1p, p_d1, ns1, n1,
                                              p_s2, nullptr, p_a2, nullptr, nullptr);
    }
    // K3: conv2 (a2 -> h_out fp32) + fused to-RGB
    {
        dim3 g(4, 32, 8);
        conv_mma_kernel<2><<<g, 256, DSMEM>>>(p_a2, p_w2p, p_d2, ns2, n2,
                                              p_sr, wr, nullptr, h_out, rgb_out);
    }
    (void)in_sizes; (void)n_in; (void)out_size;
}